// round 5
// baseline (speedup 1.0000x reference)
#include <cuda_runtime.h>
#include <cuda_bf16.h>
#include <cstdint>

// Problem constants
#define BATCH 4
#define SEQ   4096
#define DIM   1024
#define NH    16
#define HD    64
#define KVC   32              // split-S chunks for kv accumulation
#define KCH   (SEQ / KVC)     // 128

// GEMM tile config (mma.sync path — no tcgen05 on bare sm_100 target)
#define GK      1024
#define TM      128
#define TN      128
#define BK      32                   // K elements per chunk
#define NCHUNK  (GK / BK)            // 32
#define RS      40                   // smem row stride in bf16 (32 data + 8 pad) = 80B
#define TILE_B  (128 * RS * 2)       // 10240 bytes per tile
#define STAGE_B (4 * TILE_B)         // Ah, Al, Bh, Bl = 40960 bytes
#define NSTAGE  4
#define GSMEM   (NSTAGE * STAGE_B)   // 163840 bytes

// ---------------------------------------------------------------------------
// Scratch (static __device__ globals; allocation-free per harness rules)
// ---------------------------------------------------------------------------
__device__ __nv_bfloat16 g_xh[BATCH * SEQ * DIM];
__device__ __nv_bfloat16 g_xl[BATCH * SEQ * DIM];
__device__ __nv_bfloat16 g_qwh[DIM * DIM], g_qwl[DIM * DIM];
__device__ __nv_bfloat16 g_kwh[DIM * DIM], g_kwl[DIM * DIM];
__device__ __nv_bfloat16 g_vwh[DIM * DIM], g_vwl[DIM * DIM];
__device__ __nv_bfloat16 g_qh[BATCH * SEQ * DIM], g_ql[BATCH * SEQ * DIM];
__device__ float g_k[BATCH * SEQ * DIM];
__device__ float g_v[BATCH * SEQ * DIM];
__device__ float g_kvp[BATCH * NH * KVC * HD * HD];
__device__ __nv_bfloat16 g_mth[BATCH * DIM * DIM], g_mtl[BATCH * DIM * DIM];

// ---------------------------------------------------------------------------
// PTX helpers (sm_80+ compatible only: cp.async + mma.sync + ldmatrix)
// ---------------------------------------------------------------------------
__device__ __forceinline__ uint32_t smem_u32(const void* p) {
    uint32_t a;
    asm("{ .reg .u64 t; cvta.to.shared.u64 t, %1; cvt.u32.u64 %0, t; }" : "=r"(a) : "l"(p));
    return a;
}

#define CP_ASYNC16(s, g) asm volatile("cp.async.cg.shared.global [%0], [%1], 16;" :: "r"(s), "l"(g))
#define CP_COMMIT()      asm volatile("cp.async.commit_group;" ::: "memory")
#define CP_WAIT2()       asm volatile("cp.async.wait_group 2;" ::: "memory")

#define LDSM_X4(r0, r1, r2, r3, a) \
    asm volatile("ldmatrix.sync.aligned.m8n8.x4.shared.b16 {%0,%1,%2,%3}, [%4];" \
                 : "=r"(r0), "=r"(r1), "=r"(r2), "=r"(r3) : "r"(a))

// D += A * B  (m16n8k16, bf16 in, f32 accum)
__device__ __forceinline__ void mma16816(float* c, const uint32_t* a, const uint32_t* b) {
    asm volatile(
        "mma.sync.aligned.m16n8k16.row.col.f32.bf16.bf16.f32 "
        "{%0,%1,%2,%3}, {%4,%5,%6,%7}, {%8,%9}, {%0,%1,%2,%3};"
        : "+f"(c[0]), "+f"(c[1]), "+f"(c[2]), "+f"(c[3])
        : "r"(a[0]), "r"(a[1]), "r"(a[2]), "r"(a[3]), "r"(b[0]), "r"(b[1]));
}

// bf16 split helpers
__device__ __forceinline__ uint32_t pack2bf(float lo_v, float hi_v) {
    uint32_t r;
    asm("cvt.rn.bf16x2.f32 %0, %1, %2;" : "=r"(r) : "f"(hi_v), "f"(lo_v));
    return r;
}
__device__ __forceinline__ float bf16_rn(float v) {
    __nv_bfloat16 b = __float2bfloat16(v);
    return __bfloat162float(b);
}

// ---------------------------------------------------------------------------
// Split kernel: fp32 -> (bf16 hi, bf16 lo)
// ---------------------------------------------------------------------------
__global__ void split_f32_kernel(const float* __restrict__ s,
                                 __nv_bfloat16* __restrict__ ho,
                                 __nv_bfloat16* __restrict__ lo, long n)
{
    long i = ((long)blockIdx.x * blockDim.x + threadIdx.x) * 4;
    if (i >= n) return;
    float4 v = *(const float4*)(s + i);
    float hx = bf16_rn(v.x), hy = bf16_rn(v.y), hz = bf16_rn(v.z), hw = bf16_rn(v.w);
    uint2 hp = make_uint2(pack2bf(v.x, v.y), pack2bf(v.z, v.w));
    uint2 lp = make_uint2(pack2bf(v.x - hx, v.y - hy), pack2bf(v.z - hz, v.w - hw));
    *(uint2*)(ho + i) = hp;
    *(uint2*)(lo + i) = lp;
}

// ---------------------------------------------------------------------------
// HMMA GEMM: C[M,N] = A[M,K] * B[N,K]^T + bias[N], A,B pre-split bf16 (hi,lo);
// computes Ah*Bh + Ah*Bl + Al*Bh. MODE 0: fp32 out. MODE 1: split bf16 out.
// 256 threads, 128x128 tile, BK=32, 4-stage cp.async pipeline, ldmatrix frags.
// MMA issue order: 3 passes of 16 independent mmas (no same-acc RAW chains).
// ---------------------------------------------------------------------------
template <int MODE, bool RELU>
__global__ __launch_bounds__(256, 1)
void gemm_bf16x3(const __nv_bfloat16* __restrict__ Ah, const __nv_bfloat16* __restrict__ Al,
                 const __nv_bfloat16* __restrict__ Bh, const __nv_bfloat16* __restrict__ Bl,
                 const float* __restrict__ bias,
                 float* __restrict__ outF,
                 __nv_bfloat16* __restrict__ outH, __nv_bfloat16* __restrict__ outL,
                 long sA, long sB, long sC)
{
    extern __shared__ char smem[];
    const uint32_t smem_addr = smem_u32(smem);

    const int tid  = threadIdx.x;
    const int wid  = tid >> 5;
    const int lane = tid & 31;
    const int z    = blockIdx.z;
    const int m0   = blockIdx.y * TM;
    const int n0   = blockIdx.x * TN;

    Ah += (long)z * sA; Al += (long)z * sA;
    Bh += (long)z * sB; Bl += (long)z * sB;

    // Per-thread cp.async geometry: 2 (row,chunk) slots per tile
    const int r0 = (tid + 0)   >> 2, c0ck = (tid + 0)   & 3;
    const int r1 = (tid + 256) >> 2, c1ck = (tid + 256) & 3;
    const uint32_t so0 = (uint32_t)(r0 * RS + c0ck * 8) * 2;
    const uint32_t so1 = (uint32_t)(r1 * RS + c1ck * 8) * 2;
    const long ga0 = (long)(m0 + r0) * GK + c0ck * 8;
    const long ga1 = (long)(m0 + r1) * GK + c1ck * 8;
    const long gb0 = (long)(n0 + r0) * GK + c0ck * 8;
    const long gb1 = (long)(n0 + r1) * GK + c1ck * 8;

    auto load_stage = [&](int kt, int buf) {
        const uint32_t sb = smem_addr + buf * STAGE_B;
        const long ko = (long)kt * BK;
        CP_ASYNC16(sb + 0 * TILE_B + so0, Ah + ga0 + ko);
        CP_ASYNC16(sb + 0 * TILE_B + so1, Ah + ga1 + ko);
        CP_ASYNC16(sb + 1 * TILE_B + so0, Al + ga0 + ko);
        CP_ASYNC16(sb + 1 * TILE_B + so1, Al + ga1 + ko);
        CP_ASYNC16(sb + 2 * TILE_B + so0, Bh + gb0 + ko);
        CP_ASYNC16(sb + 2 * TILE_B + so1, Bh + gb1 + ko);
        CP_ASYNC16(sb + 3 * TILE_B + so0, Bl + gb0 + ko);
        CP_ASYNC16(sb + 3 * TILE_B + so1, Bl + gb1 + ko);
    };

    // Prologue: fill stages 0,1,2 of the 4-stage ring
    load_stage(0, 0); CP_COMMIT();
    load_stage(1, 1); CP_COMMIT();
    load_stage(2, 2); CP_COMMIT();

    // Warp tiling: 2x4 warp grid, each warp 64x32
    const int wm  = (wid >> 2) * 64;
    const int wn  = (wid & 3) * 32;
    const int lr  = lane >> 2;
    const int lc2 = (lane & 3) * 2;

    // ldmatrix per-lane address parts (byte offsets within a tile)
    const uint32_t rA  = lane & 15;
    const uint32_t kAp = (uint32_t)(lane >> 4) << 4;
    const uint32_t rB  = (lane & 7) + ((lane & 16) >> 1);
    const uint32_t kBp = (uint32_t)(lane & 8) << 1;

    uint32_t offA[4], offB[2];
    #pragma unroll
    for (int mt = 0; mt < 4; ++mt)
        offA[mt] = (uint32_t)(wm + mt * 16 + rA) * (RS * 2) + kAp;
    #pragma unroll
    for (int ntp = 0; ntp < 2; ++ntp)
        offB[ntp] = (uint32_t)(wn + ntp * 16 + rB) * (RS * 2) + kBp;

    float acc[4][4][4] = {};

    for (int kt = 0; kt < NCHUNK; ++kt) {
        CP_WAIT2();              // stage kt resident (always-commit keeps count uniform)
        __syncthreads();         // also: all warps finished compute(kt-1)

        // Refill ring slot (kt+3)%4 == (kt-1)%4 — consumed at kt-1, safe now
        if (kt + 3 < NCHUNK) load_stage(kt + 3, (kt + 3) & 3);
        CP_COMMIT();

        const uint32_t Sb = smem_addr + (kt & 3) * STAGE_B;

        #pragma unroll
        for (int ks2 = 0; ks2 < 2; ++ks2) {
            const uint32_t kb = ks2 * 32;   // 16 k-elements = 32 bytes
            uint32_t ah[4][4], al2[4][4], bh[4][2], bl2[4][2];

            #pragma unroll
            for (int mt = 0; mt < 4; ++mt) {
                const uint32_t aa = Sb + kb + offA[mt];
                LDSM_X4(ah[mt][0],  ah[mt][1],  ah[mt][2],  ah[mt][3],  aa);
                LDSM_X4(al2[mt][0], al2[mt][1], al2[mt][2], al2[mt][3], aa + TILE_B);
            }
            #pragma unroll
            for (int ntp = 0; ntp < 2; ++ntp) {
                const uint32_t ba = Sb + 2 * TILE_B + kb + offB[ntp];
                LDSM_X4(bh[2*ntp][0],  bh[2*ntp][1],  bh[2*ntp+1][0],  bh[2*ntp+1][1],  ba);
                LDSM_X4(bl2[2*ntp][0], bl2[2*ntp][1], bl2[2*ntp+1][0], bl2[2*ntp+1][1], ba + TILE_B);
            }

            // Pass 1: Ah*Bh — 16 independent accumulators
            #pragma unroll
            for (int mt = 0; mt < 4; ++mt)
                #pragma unroll
                for (int nt = 0; nt < 4; ++nt)
                    mma16816(acc[mt][nt], ah[mt], bh[nt]);
            // Pass 2: Ah*Bl — dependency distance 16 from pass 1
            #pragma unroll
            for (int mt = 0; mt < 4; ++mt)
                #pragma unroll
                for (int nt = 0; nt < 4; ++nt)
                    mma16816(acc[mt][nt], ah[mt], bl2[nt]);
            // Pass 3: Al*Bh
            #pragma unroll
            for (int mt = 0; mt < 4; ++mt)
                #pragma unroll
                for (int nt = 0; nt < 4; ++nt)
                    mma16816(acc[mt][nt], al2[mt], bh[nt]);
        }
    }

    // Epilogue: each thread owns (mt,nt) 2x2 f32 quads at known (row,col)
    #pragma unroll
    for (int mt = 0; mt < 4; ++mt) {
        #pragma unroll
        for (int nt = 0; nt < 4; ++nt) {
            const int row = m0 + wm + mt * 16 + lr;
            const int col = n0 + wn + nt * 8 + lc2;
            const float2 bv = *(const float2*)(bias + col);
            float v00 = acc[mt][nt][0] + bv.x, v01 = acc[mt][nt][1] + bv.y;
            float v10 = acc[mt][nt][2] + bv.x, v11 = acc[mt][nt][3] + bv.y;
            if (RELU) {
                v00 = fmaxf(v00, 0.f); v01 = fmaxf(v01, 0.f);
                v10 = fmaxf(v10, 0.f); v11 = fmaxf(v11, 0.f);
            }
            if (MODE == 0) {
                float* p = outF + (long)z * sC + (long)row * DIM + col;
                *(float2*)p                = make_float2(v00, v01);
                *(float2*)(p + 8L * DIM)   = make_float2(v10, v11);
            } else {
                const long o = (long)row * DIM + col;
                float h00 = bf16_rn(v00), h01 = bf16_rn(v01);
                float h10 = bf16_rn(v10), h11 = bf16_rn(v11);
                *(uint32_t*)(outH + o)            = pack2bf(v00, v01);
                *(uint32_t*)(outH + o + 8L * DIM) = pack2bf(v10, v11);
                *(uint32_t*)(outL + o)            = pack2bf(v00 - h00, v01 - h01);
                *(uint32_t*)(outL + o + 8L * DIM) = pack2bf(v10 - h10, v11 - h11);
            }
        }
    }
}

// ---------------------------------------------------------------------------
// kv partials: P[b,h,c,d,e] = sum_{s in chunk} k[b,s,h,d] * v[b,s,h,e]
// ---------------------------------------------------------------------------
__global__ __launch_bounds__(256)
void kv_partial()
{
    __shared__ float ks[64][64];
    __shared__ float vs[64][64];

    const int c = blockIdx.x, hh = blockIdx.y, b = blockIdx.z;
    const int t  = threadIdx.x;
    const int td = t >> 4;
    const int te = t & 15;

    const float* kb = g_k + (long)(b * SEQ + c * KCH) * DIM + hh * HD;
    const float* vb = g_v + (long)(b * SEQ + c * KCH) * DIM + hh * HD;

    float acc[4][4] = {};

    for (int sbk = 0; sbk < KCH; sbk += 64) {
        __syncthreads();
        #pragma unroll
        for (int r = 0; r < 4; ++r) {
            int idx = t + 256 * r;
            int row = idx >> 4;
            int c4  = (idx & 15) * 4;
            long g  = (long)(sbk + row) * DIM + c4;
            *(float4*)&ks[row][c4] = *(const float4*)(kb + g);
            *(float4*)&vs[row][c4] = *(const float4*)(vb + g);
        }
        __syncthreads();

        #pragma unroll 16
        for (int s = 0; s < 64; ++s) {
            float4 kf = *(const float4*)&ks[s][td * 4];
            float4 vf = *(const float4*)&vs[s][te * 4];
            float kr[4] = {kf.x, kf.y, kf.z, kf.w};
            float vr[4] = {vf.x, vf.y, vf.z, vf.w};
            #pragma unroll
            for (int i = 0; i < 4; ++i)
                #pragma unroll
                for (int j = 0; j < 4; ++j)
                    acc[i][j] += kr[i] * vr[j];
        }
    }

    float* out = g_kvp + ((long)((b * NH + hh) * KVC + c)) * HD * HD
                       + (td * 4) * HD + te * 4;
    #pragma unroll
    for (int i = 0; i < 4; ++i)
        *(float4*)(out + i * HD) = make_float4(acc[i][0], acc[i][1], acc[i][2], acc[i][3]);
}

// ---------------------------------------------------------------------------
// MT[b, j, h*64+d] = sum_e kv[b,h,d,e] * o_w[j, h*64+e]; output split to bf16
// ---------------------------------------------------------------------------
__global__ __launch_bounds__(256)
void make_mt(const float* __restrict__ OW)
{
    __shared__ float kvs[64][65];
    __shared__ float ows[64][64];

    const int jt = blockIdx.x, hh = blockIdx.y, b = blockIdx.z;
    const int t  = threadIdx.x;
    const int j0 = jt * 64;

    const float* pb = g_kvp + (long)((b * NH + hh) * KVC) * HD * HD;
    #pragma unroll
    for (int r = 0; r < 16; ++r) {
        int idx = t + 256 * r;
        float s = 0.0f;
        #pragma unroll
        for (int c = 0; c < KVC; ++c) s += pb[c * HD * HD + idx];
        kvs[idx >> 6][idx & 63] = s;
    }
    #pragma unroll
    for (int r = 0; r < 16; ++r) {
        int idx = t + 256 * r;
        int row = idx >> 6, e = idx & 63;
        ows[row][e] = OW[(long)(j0 + row) * DIM + hh * HD + e];
    }
    __syncthreads();

    const int d  = t & 63;
    const int rb = (t >> 6) * 16;
    float acc[16] = {};

    #pragma unroll 4
    for (int e = 0; e < 64; ++e) {
        float kd = kvs[d][e];
        #pragma unroll
        for (int jj = 0; jj < 16; ++jj)
            acc[jj] += ows[rb + jj][e] * kd;
    }

    long base = (long)b * DIM * DIM + hh * HD + d;
    #pragma unroll
    for (int jj = 0; jj < 16; ++jj) {
        float v = acc[jj];
        float hv = bf16_rn(v);
        long idx = base + (long)(j0 + rb + jj) * DIM;
        g_mth[idx] = __float2bfloat16(v);
        g_mtl[idx] = __float2bfloat16(v - hv);
    }
}

// ---------------------------------------------------------------------------
// Launch
// ---------------------------------------------------------------------------
template <typename T>
static T* sym_addr(const void* sym) {
    void* p = nullptr;
    cudaGetSymbolAddress(&p, sym);
    return (T*)p;
}

extern "C" void kernel_launch(void* const* d_in, const int* in_sizes, int n_in,
                              void* d_out, int out_size)
{
    (void)in_sizes; (void)n_in; (void)out_size;
    const float* x  = (const float*)d_in[0];
    const float* qw = (const float*)d_in[1];
    const float* qb = (const float*)d_in[2];
    const float* kw = (const float*)d_in[3];
    const float* kb = (const float*)d_in[4];
    const float* vw = (const float*)d_in[5];
    const float* vb = (const float*)d_in[6];
    const float* ow = (const float*)d_in[7];
    const float* ob = (const float*)d_in[8];
    float* y = (float*)d_out;

    __nv_bfloat16* xh  = sym_addr<__nv_bfloat16>(g_xh);
    __nv_bfloat16* xl  = sym_addr<__nv_bfloat16>(g_xl);
    __nv_bfloat16* qwh = sym_addr<__nv_bfloat16>(g_qwh);
    __nv_bfloat16* qwl = sym_addr<__nv_bfloat16>(g_qwl);
    __nv_bfloat16* kwh = sym_addr<__nv_bfloat16>(g_kwh);
    __nv_bfloat16* kwl = sym_addr<__nv_bfloat16>(g_kwl);
    __nv_bfloat16* vwh = sym_addr<__nv_bfloat16>(g_vwh);
    __nv_bfloat16* vwl = sym_addr<__nv_bfloat16>(g_vwl);
    __nv_bfloat16* qh  = sym_addr<__nv_bfloat16>(g_qh);
    __nv_bfloat16* ql  = sym_addr<__nv_bfloat16>(g_ql);
    float*         gk  = sym_addr<float>(g_k);
    float*         gv  = sym_addr<float>(g_v);
    __nv_bfloat16* mth = sym_addr<__nv_bfloat16>(g_mth);
    __nv_bfloat16* mtl = sym_addr<__nv_bfloat16>(g_mtl);

    cudaFuncSetAttribute(gemm_bf16x3<0, false>, cudaFuncAttributeMaxDynamicSharedMemorySize, GSMEM);
    cudaFuncSetAttribute(gemm_bf16x3<0, true >, cudaFuncAttributeMaxDynamicSharedMemorySize, GSMEM);
    cudaFuncSetAttribute(gemm_bf16x3<1, true >, cudaFuncAttributeMaxDynamicSharedMemorySize, GSMEM);

    const long NX = (long)BATCH * SEQ * DIM;   // 16.7M
    const long NW = (long)DIM * DIM;           // 1M

    // 0) split inputs/weights to bf16 hi/lo
    split_f32_kernel<<<(int)(NX / 4 / 256), 256>>>(x,  xh,  xl,  NX);
    split_f32_kernel<<<(int)(NW / 4 / 256), 256>>>(qw, qwh, qwl, NW);
    split_f32_kernel<<<(int)(NW / 4 / 256), 256>>>(kw, kwh, kwl, NW);
    split_f32_kernel<<<(int)(NW / 4 / 256), 256>>>(vw, vwh, vwl, NW);

    // 1-3) QKV projections on HMMA tensor cores
    dim3 gQKV(DIM / TN, (BATCH * SEQ) / TM, 1);
    gemm_bf16x3<1, true ><<<gQKV, 256, GSMEM>>>(xh, xl, qwh, qwl, qb, nullptr, qh, ql, 0, 0, 0);
    gemm_bf16x3<0, true ><<<gQKV, 256, GSMEM>>>(xh, xl, kwh, kwl, kb, gk, nullptr, nullptr, 0, 0, 0);
    gemm_bf16x3<0, false><<<gQKV, 256, GSMEM>>>(xh, xl, vwh, vwl, vb, gv, nullptr, nullptr, 0, 0, 0);

    // 4) kv state partials
    kv_partial<<<dim3(KVC, NH, BATCH), 256>>>();

    // 5) fold o_w into kv state, split to bf16
    make_mt<<<dim3(DIM / 64, NH, BATCH), 256>>>(ow);

    // 6) y[b] = q[b] @ MT[b]^T + o_b
    gemm_bf16x3<0, false><<<dim3(DIM / TN, SEQ / TM, BATCH), 256, GSMEM>>>(
        qh, ql, mth, mtl, ob, y, nullptr, nullptr,
        (long)SEQ * DIM, (long)DIM * DIM, (long)SEQ * DIM);
}

// round 6
// speedup vs baseline: 1.5189x; 1.5189x over previous
#include <cuda_runtime.h>
#include <cuda_fp16.h>
#include <cstdint>

// Problem constants
#define BATCH 4
#define SEQ   4096
#define DIM   1024
#define NH    16
#define HD    64
#define KVC   32              // split-S chunks for kv accumulation
#define KCH   (SEQ / KVC)     // 128

// GEMM tile config (mma.sync path — no tcgen05 on bare sm_100 target)
#define GK      1024
#define TM      128
#define TN      128
#define BK      32                   // K elements per chunk
#define NCHUNK  (GK / BK)            // 32
#define RS      40                   // smem row stride in fp16 (32 data + 8 pad) = 80B
#define TILE_B  (128 * RS * 2)       // 10240 bytes per tile
#define STAGE_B (3 * TILE_B)         // Ah, Al, B = 30720 bytes
#define NSTAGE  3
#define GSMEM   (NSTAGE * STAGE_B)   // 92160 bytes -> 2 CTAs/SM

// ---------------------------------------------------------------------------
// Scratch (static __device__ globals; allocation-free per harness rules)
// ---------------------------------------------------------------------------
__device__ __half g_xh[BATCH * SEQ * DIM];
__device__ __half g_xl[BATCH * SEQ * DIM];
__device__ __half g_qw16[DIM * DIM], g_kw16[DIM * DIM], g_vw16[DIM * DIM];
__device__ __half g_qh[BATCH * SEQ * DIM], g_ql[BATCH * SEQ * DIM];
__device__ float g_k[BATCH * SEQ * DIM];
__device__ float g_v[BATCH * SEQ * DIM];
__device__ float g_kvp[BATCH * NH * KVC * HD * HD];
__device__ __half g_mtf[BATCH * DIM * DIM];

// ---------------------------------------------------------------------------
// PTX helpers (sm_80+ compatible only: cp.async + mma.sync + ldmatrix)
// ---------------------------------------------------------------------------
__device__ __forceinline__ uint32_t smem_u32(const void* p) {
    uint32_t a;
    asm("{ .reg .u64 t; cvta.to.shared.u64 t, %1; cvt.u32.u64 %0, t; }" : "=r"(a) : "l"(p));
    return a;
}

#define CP_ASYNC16(s, g) asm volatile("cp.async.cg.shared.global [%0], [%1], 16;" :: "r"(s), "l"(g))
#define CP_COMMIT()      asm volatile("cp.async.commit_group;" ::: "memory")
#define CP_WAIT1()       asm volatile("cp.async.wait_group 1;" ::: "memory")

#define LDSM_X4(r0, r1, r2, r3, a) \
    asm volatile("ldmatrix.sync.aligned.m8n8.x4.shared.b16 {%0,%1,%2,%3}, [%4];" \
                 : "=r"(r0), "=r"(r1), "=r"(r2), "=r"(r3) : "r"(a))

// D += A * B  (m16n8k16, fp16 in, f32 accum)
__device__ __forceinline__ void mma16816(float* c, const uint32_t* a, const uint32_t* b) {
    asm volatile(
        "mma.sync.aligned.m16n8k16.row.col.f32.f16.f16.f32 "
        "{%0,%1,%2,%3}, {%4,%5,%6,%7}, {%8,%9}, {%0,%1,%2,%3};"
        : "+f"(c[0]), "+f"(c[1]), "+f"(c[2]), "+f"(c[3])
        : "r"(a[0]), "r"(a[1]), "r"(a[2]), "r"(a[3]), "r"(b[0]), "r"(b[1]));
}

// fp16 helpers
__device__ __forceinline__ uint32_t pack2h(float lo_v, float hi_v) {
    uint32_t r;
    asm("cvt.rn.f16x2.f32 %0, %1, %2;" : "=r"(r) : "f"(hi_v), "f"(lo_v));
    return r;
}
__device__ __forceinline__ float h_rn(float v) {
    return __half2float(__float2half_rn(v));
}

// ---------------------------------------------------------------------------
// Split kernel: fp32 -> (fp16 hi, fp16 lo)
// ---------------------------------------------------------------------------
__global__ void split_f32h(const float* __restrict__ s,
                           __half* __restrict__ ho,
                           __half* __restrict__ lo, long n)
{
    long i = ((long)blockIdx.x * blockDim.x + threadIdx.x) * 4;
    if (i >= n) return;
    float4 v = *(const float4*)(s + i);
    float hx = h_rn(v.x), hy = h_rn(v.y), hz = h_rn(v.z), hw = h_rn(v.w);
    *(uint2*)(ho + i) = make_uint2(pack2h(v.x, v.y), pack2h(v.z, v.w));
    *(uint2*)(lo + i) = make_uint2(pack2h(v.x - hx, v.y - hy), pack2h(v.z - hz, v.w - hw));
}

// Round kernel: fp32 -> fp16
__global__ void round_f32h(const float* __restrict__ s, __half* __restrict__ o, long n)
{
    long i = ((long)blockIdx.x * blockDim.x + threadIdx.x) * 4;
    if (i >= n) return;
    float4 v = *(const float4*)(s + i);
    *(uint2*)(o + i) = make_uint2(pack2h(v.x, v.y), pack2h(v.z, v.w));
}

// ---------------------------------------------------------------------------
// HMMA GEMM: C[M,N] = A[M,K] * B[N,K]^T + bias[N], A split fp16 (hi,lo),
// B rounded fp16; computes Ah*B + Al*B. MODE 0: fp32 out. MODE 1: split fp16.
// 256 threads, 128x128 tile, BK=32, 3-stage cp.async pipeline, ldmatrix frags.
// ---------------------------------------------------------------------------
template <int MODE, bool RELU>
__global__ __launch_bounds__(256, 2)
void gemm_f16x2(const __half* __restrict__ Ah, const __half* __restrict__ Al,
                const __half* __restrict__ B,
                const float* __restrict__ bias,
                float* __restrict__ outF,
                __half* __restrict__ outH, __half* __restrict__ outL,
                long sA, long sB, long sC)
{
    extern __shared__ char smem[];
    const uint32_t smem_addr = smem_u32(smem);

    const int tid  = threadIdx.x;
    const int wid  = tid >> 5;
    const int lane = tid & 31;
    const int z    = blockIdx.z;
    const int m0   = blockIdx.y * TM;
    const int n0   = blockIdx.x * TN;

    Ah += (long)z * sA; Al += (long)z * sA;
    B  += (long)z * sB;

    // Per-thread cp.async geometry: 2 (row,chunk) slots per tile
    const int r0 = (tid + 0)   >> 2, c0ck = (tid + 0)   & 3;
    const int r1 = (tid + 256) >> 2, c1ck = (tid + 256) & 3;
    const uint32_t so0 = (uint32_t)(r0 * RS + c0ck * 8) * 2;
    const uint32_t so1 = (uint32_t)(r1 * RS + c1ck * 8) * 2;
    const long ga0 = (long)(m0 + r0) * GK + c0ck * 8;
    const long ga1 = (long)(m0 + r1) * GK + c1ck * 8;
    const long gb0 = (long)(n0 + r0) * GK + c0ck * 8;
    const long gb1 = (long)(n0 + r1) * GK + c1ck * 8;

    auto load_stage = [&](int kt, int buf) {
        const uint32_t sb = smem_addr + buf * STAGE_B;
        const long ko = (long)kt * BK;
        CP_ASYNC16(sb + 0 * TILE_B + so0, Ah + ga0 + ko);
        CP_ASYNC16(sb + 0 * TILE_B + so1, Ah + ga1 + ko);
        CP_ASYNC16(sb + 1 * TILE_B + so0, Al + ga0 + ko);
        CP_ASYNC16(sb + 1 * TILE_B + so1, Al + ga1 + ko);
        CP_ASYNC16(sb + 2 * TILE_B + so0, B + gb0 + ko);
        CP_ASYNC16(sb + 2 * TILE_B + so1, B + gb1 + ko);
    };

    // Prologue: fill stages 0,1 of the 3-stage ring
    load_stage(0, 0); CP_COMMIT();
    load_stage(1, 1); CP_COMMIT();

    // Warp tiling: 2x4 warp grid, each warp 64x32
    const int wm  = (wid >> 2) * 64;
    const int wn  = (wid & 3) * 32;
    const int lr  = lane >> 2;
    const int lc2 = (lane & 3) * 2;

    // ldmatrix per-lane address parts (byte offsets within a tile)
    const uint32_t rA  = lane & 15;
    const uint32_t kAp = (uint32_t)(lane >> 4) << 4;
    const uint32_t rB  = (lane & 7) + ((lane & 16) >> 1);
    const uint32_t kBp = (uint32_t)(lane & 8) << 1;

    uint32_t offA[4], offB[2];
    #pragma unroll
    for (int mt = 0; mt < 4; ++mt)
        offA[mt] = (uint32_t)(wm + mt * 16 + rA) * (RS * 2) + kAp;
    #pragma unroll
    for (int ntp = 0; ntp < 2; ++ntp)
        offB[ntp] = (uint32_t)(wn + ntp * 16 + rB) * (RS * 2) + kBp;

    float acc[4][4][4] = {};

    for (int kt = 0; kt < NCHUNK; ++kt) {
        CP_WAIT1();              // stage kt resident (always-commit keeps count uniform)
        __syncthreads();         // all warps done with stage kt-1's smem

        // Refill ring slot (kt+2)%3 == (kt-1)%3 — consumed last iteration
        if (kt + 2 < NCHUNK) load_stage(kt + 2, (kt + 2) % 3);
        CP_COMMIT();

        const uint32_t Sb = smem_addr + (kt % 3) * STAGE_B;

        #pragma unroll
        for (int ks2 = 0; ks2 < 2; ++ks2) {
            const uint32_t kb = ks2 * 32;   // 16 k-elements = 32 bytes
            uint32_t ah[4][4], al2[4][4], bf[4][2];

            #pragma unroll
            for (int mt = 0; mt < 4; ++mt) {
                const uint32_t aa = Sb + kb + offA[mt];
                LDSM_X4(ah[mt][0],  ah[mt][1],  ah[mt][2],  ah[mt][3],  aa);
                LDSM_X4(al2[mt][0], al2[mt][1], al2[mt][2], al2[mt][3], aa + TILE_B);
            }
            #pragma unroll
            for (int ntp = 0; ntp < 2; ++ntp) {
                const uint32_t ba = Sb + 2 * TILE_B + kb + offB[ntp];
                LDSM_X4(bf[2*ntp][0], bf[2*ntp][1], bf[2*ntp+1][0], bf[2*ntp+1][1], ba);
            }

            // Pass 1: Ah*B — 16 independent accumulators
            #pragma unroll
            for (int mt = 0; mt < 4; ++mt)
                #pragma unroll
                for (int nt = 0; nt < 4; ++nt)
                    mma16816(acc[mt][nt], ah[mt], bf[nt]);
            // Pass 2: Al*B
            #pragma unroll
            for (int mt = 0; mt < 4; ++mt)
                #pragma unroll
                for (int nt = 0; nt < 4; ++nt)
                    mma16816(acc[mt][nt], al2[mt], bf[nt]);
        }
    }

    // Epilogue: each thread owns (mt,nt) 2x2 f32 quads at known (row,col)
    #pragma unroll
    for (int mt = 0; mt < 4; ++mt) {
        #pragma unroll
        for (int nt = 0; nt < 4; ++nt) {
            const int row = m0 + wm + mt * 16 + lr;
            const int col = n0 + wn + nt * 8 + lc2;
            const float2 bv = *(const float2*)(bias + col);
            float v00 = acc[mt][nt][0] + bv.x, v01 = acc[mt][nt][1] + bv.y;
            float v10 = acc[mt][nt][2] + bv.x, v11 = acc[mt][nt][3] + bv.y;
            if (RELU) {
                v00 = fmaxf(v00, 0.f); v01 = fmaxf(v01, 0.f);
                v10 = fmaxf(v10, 0.f); v11 = fmaxf(v11, 0.f);
            }
            if (MODE == 0) {
                float* p = outF + (long)z * sC + (long)row * DIM + col;
                *(float2*)p                = make_float2(v00, v01);
                *(float2*)(p + 8L * DIM)   = make_float2(v10, v11);
            } else {
                const long o = (long)row * DIM + col;
                float h00 = h_rn(v00), h01 = h_rn(v01);
                float h10 = h_rn(v10), h11 = h_rn(v11);
                *(uint32_t*)(outH + o)            = pack2h(v00, v01);
                *(uint32_t*)(outH + o + 8L * DIM) = pack2h(v10, v11);
                *(uint32_t*)(outL + o)            = pack2h(v00 - h00, v01 - h01);
                *(uint32_t*)(outL + o + 8L * DIM) = pack2h(v10 - h10, v11 - h11);
            }
        }
    }
}

// ---------------------------------------------------------------------------
// kv partials: P[b,h,c,d,e] = sum_{s in chunk} k[b,s,h,d] * v[b,s,h,e]
// ---------------------------------------------------------------------------
__global__ __launch_bounds__(256)
void kv_partial()
{
    __shared__ float ks[64][64];
    __shared__ float vs[64][64];

    const int c = blockIdx.x, hh = blockIdx.y, b = blockIdx.z;
    const int t  = threadIdx.x;
    const int td = t >> 4;
    const int te = t & 15;

    const float* kb = g_k + (long)(b * SEQ + c * KCH) * DIM + hh * HD;
    const float* vb = g_v + (long)(b * SEQ + c * KCH) * DIM + hh * HD;

    float acc[4][4] = {};

    for (int sbk = 0; sbk < KCH; sbk += 64) {
        __syncthreads();
        #pragma unroll
        for (int r = 0; r < 4; ++r) {
            int idx = t + 256 * r;
            int row = idx >> 4;
            int c4  = (idx & 15) * 4;
            long g  = (long)(sbk + row) * DIM + c4;
            *(float4*)&ks[row][c4] = *(const float4*)(kb + g);
            *(float4*)&vs[row][c4] = *(const float4*)(vb + g);
        }
        __syncthreads();

        #pragma unroll 16
        for (int s = 0; s < 64; ++s) {
            float4 kf = *(const float4*)&ks[s][td * 4];
            float4 vf = *(const float4*)&vs[s][te * 4];
            float kr[4] = {kf.x, kf.y, kf.z, kf.w};
            float vr[4] = {vf.x, vf.y, vf.z, vf.w};
            #pragma unroll
            for (int i = 0; i < 4; ++i)
                #pragma unroll
                for (int j = 0; j < 4; ++j)
                    acc[i][j] += kr[i] * vr[j];
        }
    }

    float* out = g_kvp + ((long)((b * NH + hh) * KVC + c)) * HD * HD
                       + (td * 4) * HD + te * 4;
    #pragma unroll
    for (int i = 0; i < 4; ++i)
        *(float4*)(out + i * HD) = make_float4(acc[i][0], acc[i][1], acc[i][2], acc[i][3]);
}

// ---------------------------------------------------------------------------
// MT[b, j, h*64+d] = sum_e kv[b,h,d,e] * o_w[j, h*64+e]; output rounded fp16
// ---------------------------------------------------------------------------
__global__ __launch_bounds__(256)
void make_mt(const float* __restrict__ OW)
{
    __shared__ float kvs[64][65];
    __shared__ float ows[64][64];

    const int jt = blockIdx.x, hh = blockIdx.y, b = blockIdx.z;
    const int t  = threadIdx.x;
    const int j0 = jt * 64;

    const float* pb = g_kvp + (long)((b * NH + hh) * KVC) * HD * HD;
    #pragma unroll
    for (int r = 0; r < 16; ++r) {
        int idx = t + 256 * r;
        float s = 0.0f;
        #pragma unroll
        for (int c = 0; c < KVC; ++c) s += pb[c * HD * HD + idx];
        kvs[idx >> 6][idx & 63] = s;
    }
    #pragma unroll
    for (int r = 0; r < 16; ++r) {
        int idx = t + 256 * r;
        int row = idx >> 6, e = idx & 63;
        ows[row][e] = OW[(long)(j0 + row) * DIM + hh * HD + e];
    }
    __syncthreads();

    const int d  = t & 63;
    const int rb = (t >> 6) * 16;
    float acc[16] = {};

    #pragma unroll 4
    for (int e = 0; e < 64; ++e) {
        float kd = kvs[d][e];
        #pragma unroll
        for (int jj = 0; jj < 16; ++jj)
            acc[jj] += ows[rb + jj][e] * kd;
    }

    long base = (long)b * DIM * DIM + hh * HD + d;
    #pragma unroll
    for (int jj = 0; jj < 16; ++jj)
        g_mtf[base + (long)(j0 + rb + jj) * DIM] = __float2half_rn(acc[jj]);
}

// ---------------------------------------------------------------------------
// Launch
// ---------------------------------------------------------------------------
template <typename T>
static T* sym_addr(const void* sym) {
    void* p = nullptr;
    cudaGetSymbolAddress(&p, sym);
    return (T*)p;
}

extern "C" void kernel_launch(void* const* d_in, const int* in_sizes, int n_in,
                              void* d_out, int out_size)
{
    (void)in_sizes; (void)n_in; (void)out_size;
    const float* x  = (const float*)d_in[0];
    const float* qw = (const float*)d_in[1];
    const float* qb = (const float*)d_in[2];
    const float* kw = (const float*)d_in[3];
    const float* kb = (const float*)d_in[4];
    const float* vw = (const float*)d_in[5];
    const float* vb = (const float*)d_in[6];
    const float* ow = (const float*)d_in[7];
    const float* ob = (const float*)d_in[8];
    float* y = (float*)d_out;

    __half* xh   = sym_addr<__half>(g_xh);
    __half* xl   = sym_addr<__half>(g_xl);
    __half* qw16 = sym_addr<__half>(g_qw16);
    __half* kw16 = sym_addr<__half>(g_kw16);
    __half* vw16 = sym_addr<__half>(g_vw16);
    __half* qh   = sym_addr<__half>(g_qh);
    __half* ql   = sym_addr<__half>(g_ql);
    float*  gk   = sym_addr<float>(g_k);
    float*  gv   = sym_addr<float>(g_v);
    __half* mtf  = sym_addr<__half>(g_mtf);

    cudaFuncSetAttribute(gemm_f16x2<0, false>, cudaFuncAttributeMaxDynamicSharedMemorySize, GSMEM);
    cudaFuncSetAttribute(gemm_f16x2<0, true >, cudaFuncAttributeMaxDynamicSharedMemorySize, GSMEM);
    cudaFuncSetAttribute(gemm_f16x2<1, true >, cudaFuncAttributeMaxDynamicSharedMemorySize, GSMEM);

    const long NX = (long)BATCH * SEQ * DIM;   // 16.7M
    const long NW = (long)DIM * DIM;           // 1M

    // 0) split x to fp16 hi/lo; round weights to fp16
    split_f32h<<<(int)(NX / 4 / 256), 256>>>(x, xh, xl, NX);
    round_f32h<<<(int)(NW / 4 / 256), 256>>>(qw, qw16, NW);
    round_f32h<<<(int)(NW / 4 / 256), 256>>>(kw, kw16, NW);
    round_f32h<<<(int)(NW / 4 / 256), 256>>>(vw, vw16, NW);

    // 1-3) QKV projections on HMMA tensor cores (2-pass fp16)
    dim3 gQKV(DIM / TN, (BATCH * SEQ) / TM, 1);
    gemm_f16x2<1, true ><<<gQKV, 256, GSMEM>>>(xh, xl, qw16, qb, nullptr, qh, ql, 0, 0, 0);
    gemm_f16x2<0, true ><<<gQKV, 256, GSMEM>>>(xh, xl, kw16, kb, gk, nullptr, nullptr, 0, 0, 0);
    gemm_f16x2<0, false><<<gQKV, 256, GSMEM>>>(xh, xl, vw16, vb, gv, nullptr, nullptr, 0, 0, 0);

    // 4) kv state partials
    kv_partial<<<dim3(KVC, NH, BATCH), 256>>>();

    // 5) fold o_w into kv state, round to fp16
    make_mt<<<dim3(DIM / 64, NH, BATCH), 256>>>(ow);

    // 6) y[b] = q[b] @ MT[b]^T + o_b
    gemm_f16x2<0, false><<<dim3(DIM / TN, SEQ / TM, BATCH), 256, GSMEM>>>(
        qh, ql, mtf, ob, y, nullptr, nullptr,
        (long)SEQ * DIM, (long)DIM * DIM, (long)SEQ * DIM);
}

// round 7
// speedup vs baseline: 2.3444x; 1.5435x over previous
#include <cuda_runtime.h>
#include <cuda_fp16.h>
#include <cstdint>

// Problem constants
#define BATCH 4
#define SEQ   4096
#define DIM   1024
#define NH    16
#define HD    64
#define KVC   32              // split-S chunks for kv accumulation
#define KCH   (SEQ / KVC)     // 128

// GEMM tile config (mma.sync path — no tcgen05 on bare sm_100 target)
#define GK      1024
#define TM      128
#define TN      128
#define BK      32                   // K elements per chunk
#define NCHUNK  (GK / BK)            // 32
#define RS      40                   // smem row stride in fp16 (32 data + 8 pad) = 80B
#define TILE_B  (128 * RS * 2)       // 10240 bytes per tile
#define STAGE_B (2 * TILE_B)         // A, B = 20480 bytes
#define NSTAGE  4
#define GSMEM   (NSTAGE * STAGE_B)   // 81920 bytes -> 2 CTAs/SM

// ---------------------------------------------------------------------------
// Scratch (static __device__ globals; allocation-free per harness rules)
// ---------------------------------------------------------------------------
__device__ __half g_x16[BATCH * SEQ * DIM];
__device__ __half g_qw16[DIM * DIM], g_kw16[DIM * DIM], g_vw16[DIM * DIM];
__device__ __half g_q16[BATCH * SEQ * DIM];
__device__ __half g_k16[BATCH * SEQ * DIM];
__device__ __half g_v16[BATCH * SEQ * DIM];
__device__ float g_kvp[BATCH * NH * KVC * HD * HD];
__device__ __half g_mtf[BATCH * DIM * DIM];

// ---------------------------------------------------------------------------
// PTX helpers (sm_80+ compatible only: cp.async + mma.sync + ldmatrix)
// ---------------------------------------------------------------------------
__device__ __forceinline__ uint32_t smem_u32(const void* p) {
    uint32_t a;
    asm("{ .reg .u64 t; cvta.to.shared.u64 t, %1; cvt.u32.u64 %0, t; }" : "=r"(a) : "l"(p));
    return a;
}

#define CP_ASYNC16(s, g) asm volatile("cp.async.cg.shared.global [%0], [%1], 16;" :: "r"(s), "l"(g))
#define CP_COMMIT()      asm volatile("cp.async.commit_group;" ::: "memory")
#define CP_WAIT2()       asm volatile("cp.async.wait_group 2;" ::: "memory")

#define LDSM_X4(r0, r1, r2, r3, a) \
    asm volatile("ldmatrix.sync.aligned.m8n8.x4.shared.b16 {%0,%1,%2,%3}, [%4];" \
                 : "=r"(r0), "=r"(r1), "=r"(r2), "=r"(r3) : "r"(a))

// D += A * B  (m16n8k16, fp16 in, f32 accum)
__device__ __forceinline__ void mma16816(float* c, const uint32_t* a, const uint32_t* b) {
    asm volatile(
        "mma.sync.aligned.m16n8k16.row.col.f32.f16.f16.f32 "
        "{%0,%1,%2,%3}, {%4,%5,%6,%7}, {%8,%9}, {%0,%1,%2,%3};"
        : "+f"(c[0]), "+f"(c[1]), "+f"(c[2]), "+f"(c[3])
        : "r"(a[0]), "r"(a[1]), "r"(a[2]), "r"(a[3]), "r"(b[0]), "r"(b[1]));
}

// fp16 helpers
__device__ __forceinline__ uint32_t pack2h(float lo_v, float hi_v) {
    uint32_t r;
    asm("cvt.rn.f16x2.f32 %0, %1, %2;" : "=r"(r) : "f"(hi_v), "f"(lo_v));
    return r;
}

// ---------------------------------------------------------------------------
// Round kernels: fp32 -> fp16
// ---------------------------------------------------------------------------
__global__ void round_f32h(const float* __restrict__ s, __half* __restrict__ o, long n)
{
    long i = ((long)blockIdx.x * blockDim.x + threadIdx.x) * 4;
    if (i >= n) return;
    float4 v = *(const float4*)(s + i);
    *(uint2*)(o + i) = make_uint2(pack2h(v.x, v.y), pack2h(v.z, v.w));
}

// Round 3 weight matrices in one launch (blockIdx.y selects)
__global__ void round_w3(const float* __restrict__ s0, const float* __restrict__ s1,
                         const float* __restrict__ s2,
                         __half* __restrict__ o0, __half* __restrict__ o1,
                         __half* __restrict__ o2, long n)
{
    const float* s = (blockIdx.y == 0) ? s0 : (blockIdx.y == 1) ? s1 : s2;
    __half*      o = (blockIdx.y == 0) ? o0 : (blockIdx.y == 1) ? o1 : o2;
    long i = ((long)blockIdx.x * blockDim.x + threadIdx.x) * 4;
    if (i >= n) return;
    float4 v = *(const float4*)(s + i);
    *(uint2*)(o + i) = make_uint2(pack2h(v.x, v.y), pack2h(v.z, v.w));
}

// ---------------------------------------------------------------------------
// HMMA GEMM (single-pass fp16): C[M,N] = A[M,K] * B[N,K]^T + bias[N].
// MODE 0: fp32 out. MODE 1: fp16 out. Optional ReLU.
// 256 threads, 128x128 tile, BK=32, 4-stage cp.async pipeline, ldmatrix frags.
// ---------------------------------------------------------------------------
template <int MODE, bool RELU>
__global__ __launch_bounds__(256, 2)
void gemm_f16(const __half* __restrict__ A, const __half* __restrict__ B,
              const float* __restrict__ bias,
              float* __restrict__ outF, __half* __restrict__ outH,
              long sA, long sB, long sC)
{
    extern __shared__ char smem[];
    const uint32_t smem_addr = smem_u32(smem);

    const int tid  = threadIdx.x;
    const int wid  = tid >> 5;
    const int lane = tid & 31;
    const int z    = blockIdx.z;
    const int m0   = blockIdx.y * TM;
    const int n0   = blockIdx.x * TN;

    A += (long)z * sA;
    B += (long)z * sB;

    // Per-thread cp.async geometry: 2 (row,chunk) slots per tile
    const int r0 = (tid + 0)   >> 2, c0ck = (tid + 0)   & 3;
    const int r1 = (tid + 256) >> 2, c1ck = (tid + 256) & 3;
    const uint32_t so0 = (uint32_t)(r0 * RS + c0ck * 8) * 2;
    const uint32_t so1 = (uint32_t)(r1 * RS + c1ck * 8) * 2;
    const long ga0 = (long)(m0 + r0) * GK + c0ck * 8;
    const long ga1 = (long)(m0 + r1) * GK + c1ck * 8;
    const long gb0 = (long)(n0 + r0) * GK + c0ck * 8;
    const long gb1 = (long)(n0 + r1) * GK + c1ck * 8;

    auto load_stage = [&](int kt, int buf) {
        const uint32_t sb = smem_addr + buf * STAGE_B;
        const long ko = (long)kt * BK;
        CP_ASYNC16(sb + so0,          A + ga0 + ko);
        CP_ASYNC16(sb + so1,          A + ga1 + ko);
        CP_ASYNC16(sb + TILE_B + so0, B + gb0 + ko);
        CP_ASYNC16(sb + TILE_B + so1, B + gb1 + ko);
    };

    // Prologue: fill stages 0,1,2 of the 4-stage ring
    load_stage(0, 0); CP_COMMIT();
    load_stage(1, 1); CP_COMMIT();
    load_stage(2, 2); CP_COMMIT();

    // Warp tiling: 2x4 warp grid, each warp 64x32
    const int wm  = (wid >> 2) * 64;
    const int wn  = (wid & 3) * 32;
    const int lr  = lane >> 2;
    const int lc2 = (lane & 3) * 2;

    // ldmatrix per-lane address parts (byte offsets within a tile)
    const uint32_t rA  = lane & 15;
    const uint32_t kAp = (uint32_t)(lane >> 4) << 4;
    const uint32_t rB  = (lane & 7) + ((lane & 16) >> 1);
    const uint32_t kBp = (uint32_t)(lane & 8) << 1;

    uint32_t offA[4], offB[2];
    #pragma unroll
    for (int mt = 0; mt < 4; ++mt)
        offA[mt] = (uint32_t)(wm + mt * 16 + rA) * (RS * 2) + kAp;
    #pragma unroll
    for (int ntp = 0; ntp < 2; ++ntp)
        offB[ntp] = (uint32_t)(wn + ntp * 16 + rB) * (RS * 2) + kBp;

    float acc[4][4][4] = {};

    for (int kt = 0; kt < NCHUNK; ++kt) {
        CP_WAIT2();              // stage kt resident (always-commit keeps count uniform)
        __syncthreads();         // all warps done with stage (kt-1)'s smem

        // Refill ring slot (kt+3)%4 == (kt-1)%4 — consumed last iteration
        if (kt + 3 < NCHUNK) load_stage(kt + 3, (kt + 3) & 3);
        CP_COMMIT();

        const uint32_t Sb = smem_addr + (kt & 3) * STAGE_B;

        #pragma unroll
        for (int ks2 = 0; ks2 < 2; ++ks2) {
            const uint32_t kb = ks2 * 32;   // 16 k-elements = 32 bytes
            uint32_t af[4][4], bf[4][2];

            #pragma unroll
            for (int mt = 0; mt < 4; ++mt)
                LDSM_X4(af[mt][0], af[mt][1], af[mt][2], af[mt][3], Sb + kb + offA[mt]);
            #pragma unroll
            for (int ntp = 0; ntp < 2; ++ntp) {
                const uint32_t ba = Sb + TILE_B + kb + offB[ntp];
                LDSM_X4(bf[2*ntp][0], bf[2*ntp][1], bf[2*ntp+1][0], bf[2*ntp+1][1], ba);
            }

            #pragma unroll
            for (int mt = 0; mt < 4; ++mt)
                #pragma unroll
                for (int nt = 0; nt < 4; ++nt)
                    mma16816(acc[mt][nt], af[mt], bf[nt]);
        }
    }

    // Epilogue: each thread owns (mt,nt) 2x2 f32 quads at known (row,col)
    #pragma unroll
    for (int mt = 0; mt < 4; ++mt) {
        #pragma unroll
        for (int nt = 0; nt < 4; ++nt) {
            const int row = m0 + wm + mt * 16 + lr;
            const int col = n0 + wn + nt * 8 + lc2;
            const float2 bv = *(const float2*)(bias + col);
            float v00 = acc[mt][nt][0] + bv.x, v01 = acc[mt][nt][1] + bv.y;
            float v10 = acc[mt][nt][2] + bv.x, v11 = acc[mt][nt][3] + bv.y;
            if (RELU) {
                v00 = fmaxf(v00, 0.f); v01 = fmaxf(v01, 0.f);
                v10 = fmaxf(v10, 0.f); v11 = fmaxf(v11, 0.f);
            }
            if (MODE == 0) {
                float* p = outF + (long)z * sC + (long)row * DIM + col;
                *(float2*)p              = make_float2(v00, v01);
                *(float2*)(p + 8L * DIM) = make_float2(v10, v11);
            } else {
                const long o = (long)row * DIM + col;
                *(uint32_t*)(outH + o)            = pack2h(v00, v01);
                *(uint32_t*)(outH + o + 8L * DIM) = pack2h(v10, v11);
            }
        }
    }
}

// ---------------------------------------------------------------------------
// kv partials: P[b,h,c,d,e] = sum_{s in chunk} k[b,s,h,d] * v[b,s,h,e]
// Consumes fp16 k/v, fp32 accumulate.
// ---------------------------------------------------------------------------
__global__ __launch_bounds__(256)
void kv_partial()
{
    __shared__ float ks[64][64];
    __shared__ float vs[64][64];

    const int c = blockIdx.x, hh = blockIdx.y, b = blockIdx.z;
    const int t  = threadIdx.x;
    const int td = t >> 4;
    const int te = t & 15;

    const __half* kb = g_k16 + (long)(b * SEQ + c * KCH) * DIM + hh * HD;
    const __half* vb = g_v16 + (long)(b * SEQ + c * KCH) * DIM + hh * HD;

    float acc[4][4] = {};

    for (int sbk = 0; sbk < KCH; sbk += 64) {
        __syncthreads();
        #pragma unroll
        for (int r = 0; r < 2; ++r) {
            int idx = t + 256 * r;          // 512 slots of 8 halves
            int row = idx >> 3;
            int c8  = (idx & 7) * 8;
            long g  = (long)(sbk + row) * DIM + c8;
            uint4 kp = *(const uint4*)(kb + g);
            uint4 vp = *(const uint4*)(vb + g);
            const __half2* k2 = (const __half2*)&kp;
            const __half2* v2 = (const __half2*)&vp;
            #pragma unroll
            for (int j = 0; j < 4; ++j) {
                float2 kf = __half22float2(k2[j]);
                float2 vf = __half22float2(v2[j]);
                ks[row][c8 + 2*j]     = kf.x;
                ks[row][c8 + 2*j + 1] = kf.y;
                vs[row][c8 + 2*j]     = vf.x;
                vs[row][c8 + 2*j + 1] = vf.y;
            }
        }
        __syncthreads();

        #pragma unroll 16
        for (int s = 0; s < 64; ++s) {
            float4 kf = *(const float4*)&ks[s][td * 4];
            float4 vf = *(const float4*)&vs[s][te * 4];
            float kr[4] = {kf.x, kf.y, kf.z, kf.w};
            float vr[4] = {vf.x, vf.y, vf.z, vf.w};
            #pragma unroll
            for (int i = 0; i < 4; ++i)
                #pragma unroll
                for (int j = 0; j < 4; ++j)
                    acc[i][j] += kr[i] * vr[j];
        }
    }

    float* out = g_kvp + ((long)((b * NH + hh) * KVC + c)) * HD * HD
                       + (td * 4) * HD + te * 4;
    #pragma unroll
    for (int i = 0; i < 4; ++i)
        *(float4*)(out + i * HD) = make_float4(acc[i][0], acc[i][1], acc[i][2], acc[i][3]);
}

// ---------------------------------------------------------------------------
// MT[b, j, h*64+d] = sum_e kv[b,h,d,e] * o_w[j, h*64+e]; output rounded fp16
// ---------------------------------------------------------------------------
__global__ __launch_bounds__(256)
void make_mt(const float* __restrict__ OW)
{
    __shared__ float kvs[64][65];
    __shared__ float ows[64][64];

    const int jt = blockIdx.x, hh = blockIdx.y, b = blockIdx.z;
    const int t  = threadIdx.x;
    const int j0 = jt * 64;

    const float* pb = g_kvp + (long)((b * NH + hh) * KVC) * HD * HD;
    #pragma unroll
    for (int r = 0; r < 16; ++r) {
        int idx = t + 256 * r;
        float s = 0.0f;
        #pragma unroll
        for (int c = 0; c < KVC; ++c) s += pb[c * HD * HD + idx];
        kvs[idx >> 6][idx & 63] = s;
    }
    #pragma unroll
    for (int r = 0; r < 16; ++r) {
        int idx = t + 256 * r;
        int row = idx >> 6, e = idx & 63;
        ows[row][e] = OW[(long)(j0 + row) * DIM + hh * HD + e];
    }
    __syncthreads();

    const int d  = t & 63;
    const int rb = (t >> 6) * 16;
    float acc[16] = {};

    #pragma unroll 4
    for (int e = 0; e < 64; ++e) {
        float kd = kvs[d][e];
        #pragma unroll
        for (int jj = 0; jj < 16; ++jj)
            acc[jj] += ows[rb + jj][e] * kd;
    }

    long base = (long)b * DIM * DIM + hh * HD + d;
    #pragma unroll
    for (int jj = 0; jj < 16; ++jj)
        g_mtf[base + (long)(j0 + rb + jj) * DIM] = __float2half_rn(acc[jj]);
}

// ---------------------------------------------------------------------------
// Launch
// ---------------------------------------------------------------------------
template <typename T>
static T* sym_addr(const void* sym) {
    void* p = nullptr;
    cudaGetSymbolAddress(&p, sym);
    return (T*)p;
}

extern "C" void kernel_launch(void* const* d_in, const int* in_sizes, int n_in,
                              void* d_out, int out_size)
{
    (void)in_sizes; (void)n_in; (void)out_size;
    const float* x  = (const float*)d_in[0];
    const float* qw = (const float*)d_in[1];
    const float* qb = (const float*)d_in[2];
    const float* kw = (const float*)d_in[3];
    const float* kb = (const float*)d_in[4];
    const float* vw = (const float*)d_in[5];
    const float* vb = (const float*)d_in[6];
    const float* ow = (const float*)d_in[7];
    const float* ob = (const float*)d_in[8];
    float* y = (float*)d_out;

    __half* x16  = sym_addr<__half>(g_x16);
    __half* qw16 = sym_addr<__half>(g_qw16);
    __half* kw16 = sym_addr<__half>(g_kw16);
    __half* vw16 = sym_addr<__half>(g_vw16);
    __half* q16  = sym_addr<__half>(g_q16);
    __half* k16  = sym_addr<__half>(g_k16);
    __half* v16  = sym_addr<__half>(g_v16);
    __half* mtf  = sym_addr<__half>(g_mtf);

    cudaFuncSetAttribute(gemm_f16<0, false>, cudaFuncAttributeMaxDynamicSharedMemorySize, GSMEM);
    cudaFuncSetAttribute(gemm_f16<1, true >, cudaFuncAttributeMaxDynamicSharedMemorySize, GSMEM);
    cudaFuncSetAttribute(gemm_f16<1, false>, cudaFuncAttributeMaxDynamicSharedMemorySize, GSMEM);

    const long NX = (long)BATCH * SEQ * DIM;   // 16.7M
    const long NW = (long)DIM * DIM;           // 1M

    // 0) round x and weights to fp16
    round_f32h<<<(int)(NX / 4 / 256), 256>>>(x, x16, NX);
    round_w3<<<dim3((int)(NW / 4 / 256), 3, 1), 256>>>(qw, kw, vw, qw16, kw16, vw16, NW);

    // 1-3) QKV projections on HMMA tensor cores (single-pass fp16)
    dim3 gQKV(DIM / TN, (BATCH * SEQ) / TM, 1);
    gemm_f16<1, true ><<<gQKV, 256, GSMEM>>>(x16, qw16, qb, nullptr, q16, 0, 0, 0);
    gemm_f16<1, true ><<<gQKV, 256, GSMEM>>>(x16, kw16, kb, nullptr, k16, 0, 0, 0);
    gemm_f16<1, false><<<gQKV, 256, GSMEM>>>(x16, vw16, vb, nullptr, v16, 0, 0, 0);

    // 4) kv state partials (fp16 in, fp32 accum)
    kv_partial<<<dim3(KVC, NH, BATCH), 256>>>();

    // 5) fold o_w into kv state, round to fp16
    make_mt<<<dim3(DIM / 64, NH, BATCH), 256>>>(ow);

    // 6) y[b] = q[b] @ MT[b]^T + o_b
    gemm_f16<0, false><<<dim3(DIM / TN, SEQ / TM, BATCH), 256, GSMEM>>>(
        q16, mtf, ob, y, nullptr,
        (long)SEQ * DIM, (long)DIM * DIM, (long)SEQ * DIM);
}

// round 8
// speedup vs baseline: 2.5842x; 1.1023x over previous
#include <cuda_runtime.h>
#include <cuda_fp16.h>
#include <cstdint>

// Problem constants
#define BATCH 4
#define SEQ   4096
#define DIM   1024
#define NH    16
#define HD    64
#define KVC   32              // split-S chunks for kv accumulation
#define KCH   (SEQ / KVC)     // 128

// GEMM tile config (mma.sync path — no tcgen05 on bare sm_100 target)
#define GK      1024
#define TM      128
#define TN      128
#define BK      64                   // K elements per chunk
#define NCHUNK  (GK / BK)            // 16
#define RS      72                   // smem row stride in fp16 (64 data + 8 pad) = 144B
#define TILE_B  (128 * RS * 2)       // 18432 bytes per tile
#define STAGE_B (2 * TILE_B)         // A, B = 36864 bytes
#define NSTAGE  3
#define GSMEM   (NSTAGE * STAGE_B)   // 110592 bytes -> 2 CTAs/SM (221KB < 228KB)

// ---------------------------------------------------------------------------
// Scratch (static __device__ globals; allocation-free per harness rules)
// ---------------------------------------------------------------------------
__device__ __half g_x16[BATCH * SEQ * DIM];
__device__ __half g_qw16[DIM * DIM], g_kw16[DIM * DIM], g_vw16[DIM * DIM];
__device__ __half g_q16[BATCH * SEQ * DIM];
__device__ __half g_k16[BATCH * SEQ * DIM];
__device__ __half g_v16[BATCH * SEQ * DIM];
__device__ float g_kvp[BATCH * NH * KVC * HD * HD];
__device__ __half g_mtf[BATCH * DIM * DIM];

// ---------------------------------------------------------------------------
// PTX helpers (sm_80+ compatible only: cp.async + mma.sync + ldmatrix)
// ---------------------------------------------------------------------------
__device__ __forceinline__ uint32_t smem_u32(const void* p) {
    uint32_t a;
    asm("{ .reg .u64 t; cvta.to.shared.u64 t, %1; cvt.u32.u64 %0, t; }" : "=r"(a) : "l"(p));
    return a;
}

#define CP_ASYNC16(s, g) asm volatile("cp.async.cg.shared.global [%0], [%1], 16;" :: "r"(s), "l"(g))
#define CP_COMMIT()      asm volatile("cp.async.commit_group;" ::: "memory")
#define CP_WAIT1()       asm volatile("cp.async.wait_group 1;" ::: "memory")

#define LDSM_X4(r0, r1, r2, r3, a) \
    asm volatile("ldmatrix.sync.aligned.m8n8.x4.shared.b16 {%0,%1,%2,%3}, [%4];" \
                 : "=r"(r0), "=r"(r1), "=r"(r2), "=r"(r3) : "r"(a))

// D += A * B  (m16n8k16, fp16 in, f32 accum)
__device__ __forceinline__ void mma16816(float* c, const uint32_t* a, const uint32_t* b) {
    asm volatile(
        "mma.sync.aligned.m16n8k16.row.col.f32.f16.f16.f32 "
        "{%0,%1,%2,%3}, {%4,%5,%6,%7}, {%8,%9}, {%0,%1,%2,%3};"
        : "+f"(c[0]), "+f"(c[1]), "+f"(c[2]), "+f"(c[3])
        : "r"(a[0]), "r"(a[1]), "r"(a[2]), "r"(a[3]), "r"(b[0]), "r"(b[1]));
}

// fp16 helpers
__device__ __forceinline__ uint32_t pack2h(float lo_v, float hi_v) {
    uint32_t r;
    asm("cvt.rn.f16x2.f32 %0, %1, %2;" : "=r"(r) : "f"(hi_v), "f"(lo_v));
    return r;
}

// ---------------------------------------------------------------------------
// Round kernels: fp32 -> fp16
// ---------------------------------------------------------------------------
__global__ void round_f32h(const float* __restrict__ s, __half* __restrict__ o, long n)
{
    long i = ((long)blockIdx.x * blockDim.x + threadIdx.x) * 4;
    if (i >= n) return;
    float4 v = *(const float4*)(s + i);
    *(uint2*)(o + i) = make_uint2(pack2h(v.x, v.y), pack2h(v.z, v.w));
}

__global__ void round_w3(const float* __restrict__ s0, const float* __restrict__ s1,
                         const float* __restrict__ s2,
                         __half* __restrict__ o0, __half* __restrict__ o1,
                         __half* __restrict__ o2, long n)
{
    const float* s = (blockIdx.y == 0) ? s0 : (blockIdx.y == 1) ? s1 : s2;
    __half*      o = (blockIdx.y == 0) ? o0 : (blockIdx.y == 1) ? o1 : o2;
    long i = ((long)blockIdx.x * blockDim.x + threadIdx.x) * 4;
    if (i >= n) return;
    float4 v = *(const float4*)(s + i);
    *(uint2*)(o + i) = make_uint2(pack2h(v.x, v.y), pack2h(v.z, v.w));
}

// ---------------------------------------------------------------------------
// Shared GEMM mainloop: acc[4][4][4] += A_tile[m0:128, :] * B_tile[n0:128, :]^T
// 256 threads, 128x128 tile, BK=64, 3-stage cp.async pipeline, ldmatrix frags.
// ---------------------------------------------------------------------------
__device__ __forceinline__ void gemm_mainloop(
    const __half* __restrict__ A, const __half* __restrict__ B,
    uint32_t smem_addr, int m0, int n0, int tid, float acc[4][4][4])
{
    const int wid  = tid >> 5;
    const int lane = tid & 31;

    // Per-thread cp.async geometry: 4 (row,16B-chunk) slots per tile
    uint32_t so[4];
    long ga[4], gb[4];
    #pragma unroll
    for (int i = 0; i < 4; ++i) {
        int idx = i * 256 + tid;
        int row = idx >> 3, ck = idx & 7;
        so[i] = (uint32_t)(row * RS + ck * 8) * 2;
        ga[i] = (long)(m0 + row) * GK + ck * 8;
        gb[i] = (long)(n0 + row) * GK + ck * 8;
    }

    auto load_stage = [&](int kt, int buf) {
        const uint32_t sb = smem_addr + buf * STAGE_B;
        const long ko = (long)kt * BK;
        #pragma unroll
        for (int i = 0; i < 4; ++i) CP_ASYNC16(sb + so[i],          A + ga[i] + ko);
        #pragma unroll
        for (int i = 0; i < 4; ++i) CP_ASYNC16(sb + TILE_B + so[i], B + gb[i] + ko);
    };

    // Prologue: fill stages 0,1 of the 3-stage ring
    load_stage(0, 0); CP_COMMIT();
    load_stage(1, 1); CP_COMMIT();

    // Warp tiling: 2x4 warp grid, each warp 64x32
    const int wm = (wid >> 2) * 64;
    const int wn = (wid & 3) * 32;

    // ldmatrix per-lane address parts (byte offsets within a tile)
    const uint32_t rA  = lane & 15;
    const uint32_t kAp = (uint32_t)(lane >> 4) << 4;
    const uint32_t rB  = (lane & 7) + ((lane & 16) >> 1);
    const uint32_t kBp = (uint32_t)(lane & 8) << 1;

    uint32_t offA[4], offB[2];
    #pragma unroll
    for (int mt = 0; mt < 4; ++mt)
        offA[mt] = (uint32_t)(wm + mt * 16 + rA) * (RS * 2) + kAp;
    #pragma unroll
    for (int ntp = 0; ntp < 2; ++ntp)
        offB[ntp] = (uint32_t)(wn + ntp * 16 + rB) * (RS * 2) + kBp;

    for (int kt = 0; kt < NCHUNK; ++kt) {
        CP_WAIT1();              // stage kt resident
        __syncthreads();         // all warps done with stage (kt-1)'s smem

        if (kt + 2 < NCHUNK) load_stage(kt + 2, (kt + 2) % 3);
        CP_COMMIT();             // always commit: uniform group counts

        const uint32_t Sb = smem_addr + (kt % 3) * STAGE_B;

        #pragma unroll
        for (int ks2 = 0; ks2 < 4; ++ks2) {
            const uint32_t kb = ks2 * 32;   // 16 k-elements = 32 bytes
            uint32_t af[4][4], bf[4][2];

            #pragma unroll
            for (int mt = 0; mt < 4; ++mt)
                LDSM_X4(af[mt][0], af[mt][1], af[mt][2], af[mt][3], Sb + kb + offA[mt]);
            #pragma unroll
            for (int ntp = 0; ntp < 2; ++ntp) {
                const uint32_t ba = Sb + TILE_B + kb + offB[ntp];
                LDSM_X4(bf[2*ntp][0], bf[2*ntp][1], bf[2*ntp+1][0], bf[2*ntp+1][1], ba);
            }

            #pragma unroll
            for (int mt = 0; mt < 4; ++mt)
                #pragma unroll
                for (int nt = 0; nt < 4; ++nt)
                    mma16816(acc[mt][nt], af[mt], bf[nt]);
        }
    }
}

// ---------------------------------------------------------------------------
// Fused QKV GEMM: blockIdx.z selects (W, bias, out, relu). fp16 out.
// ---------------------------------------------------------------------------
__global__ __launch_bounds__(256, 2)
void gemm_qkv(const float* __restrict__ qb, const float* __restrict__ kb,
              const float* __restrict__ vb)
{
    extern __shared__ char smem[];
    const uint32_t smem_addr = smem_u32(smem);

    const int tid = threadIdx.x;
    const int z   = blockIdx.z;
    const int m0  = blockIdx.y * TM;
    const int n0  = blockIdx.x * TN;

    const __half* B    = (z == 0) ? g_qw16 : (z == 1) ? g_kw16 : g_vw16;
    const float*  bias = (z == 0) ? qb     : (z == 1) ? kb     : vb;
    __half*       outH = (z == 0) ? g_q16  : (z == 1) ? g_k16  : g_v16;
    const bool    relu = (z != 2);

    float acc[4][4][4] = {};
    gemm_mainloop(g_x16, B, smem_addr, m0, n0, tid, acc);

    const int wid  = tid >> 5;
    const int lane = tid & 31;
    const int wm = (wid >> 2) * 64, wn = (wid & 3) * 32;
    const int lr = lane >> 2, lc2 = (lane & 3) * 2;

    #pragma unroll
    for (int mt = 0; mt < 4; ++mt) {
        #pragma unroll
        for (int nt = 0; nt < 4; ++nt) {
            const int row = m0 + wm + mt * 16 + lr;
            const int col = n0 + wn + nt * 8 + lc2;
            const float2 bv = *(const float2*)(bias + col);
            float v00 = acc[mt][nt][0] + bv.x, v01 = acc[mt][nt][1] + bv.y;
            float v10 = acc[mt][nt][2] + bv.x, v11 = acc[mt][nt][3] + bv.y;
            if (relu) {
                v00 = fmaxf(v00, 0.f); v01 = fmaxf(v01, 0.f);
                v10 = fmaxf(v10, 0.f); v11 = fmaxf(v11, 0.f);
            }
            const long o = (long)row * DIM + col;
            *(uint32_t*)(outH + o)            = pack2h(v00, v01);
            *(uint32_t*)(outH + o + 8L * DIM) = pack2h(v10, v11);
        }
    }
}

// ---------------------------------------------------------------------------
// Final GEMM: y[b] = q[b] @ MT[b]^T + o_b  (fp32 out, blockIdx.z = batch)
// ---------------------------------------------------------------------------
__global__ __launch_bounds__(256, 2)
void gemm_out(const float* __restrict__ bias, float* __restrict__ outF)
{
    extern __shared__ char smem[];
    const uint32_t smem_addr = smem_u32(smem);

    const int tid = threadIdx.x;
    const int z   = blockIdx.z;
    const int m0  = blockIdx.y * TM;
    const int n0  = blockIdx.x * TN;

    const __half* A = g_q16 + (long)z * SEQ * DIM;
    const __half* B = g_mtf + (long)z * DIM * DIM;

    float acc[4][4][4] = {};
    gemm_mainloop(A, B, smem_addr, m0, n0, tid, acc);

    const int wid  = tid >> 5;
    const int lane = tid & 31;
    const int wm = (wid >> 2) * 64, wn = (wid & 3) * 32;
    const int lr = lane >> 2, lc2 = (lane & 3) * 2;

    float* out = outF + (long)z * SEQ * DIM;

    #pragma unroll
    for (int mt = 0; mt < 4; ++mt) {
        #pragma unroll
        for (int nt = 0; nt < 4; ++nt) {
            const int row = m0 + wm + mt * 16 + lr;
            const int col = n0 + wn + nt * 8 + lc2;
            const float2 bv = *(const float2*)(bias + col);
            float* p = out + (long)row * DIM + col;
            *(float2*)p              = make_float2(acc[mt][nt][0] + bv.x, acc[mt][nt][1] + bv.y);
            *(float2*)(p + 8L * DIM) = make_float2(acc[mt][nt][2] + bv.x, acc[mt][nt][3] + bv.y);
        }
    }
}

// ---------------------------------------------------------------------------
// kv partials: P[b,h,c,d,e] = sum_{s in chunk} k[b,s,h,d] * v[b,s,h,e]
// ---------------------------------------------------------------------------
__global__ __launch_bounds__(256)
void kv_partial()
{
    __shared__ float ks[64][64];
    __shared__ float vs[64][64];

    const int c = blockIdx.x, hh = blockIdx.y, b = blockIdx.z;
    const int t  = threadIdx.x;
    const int td = t >> 4;
    const int te = t & 15;

    const __half* kb = g_k16 + (long)(b * SEQ + c * KCH) * DIM + hh * HD;
    const __half* vb = g_v16 + (long)(b * SEQ + c * KCH) * DIM + hh * HD;

    float acc[4][4] = {};

    for (int sbk = 0; sbk < KCH; sbk += 64) {
        __syncthreads();
        #pragma unroll
        for (int r = 0; r < 2; ++r) {
            int idx = t + 256 * r;
            int row = idx >> 3;
            int c8  = (idx & 7) * 8;
            long g  = (long)(sbk + row) * DIM + c8;
            uint4 kp = *(const uint4*)(kb + g);
            uint4 vp = *(const uint4*)(vb + g);
            const __half2* k2 = (const __half2*)&kp;
            const __half2* v2 = (const __half2*)&vp;
            #pragma unroll
            for (int j = 0; j < 4; ++j) {
                float2 kf = __half22float2(k2[j]);
                float2 vf = __half22float2(v2[j]);
                ks[row][c8 + 2*j]     = kf.x;
                ks[row][c8 + 2*j + 1] = kf.y;
                vs[row][c8 + 2*j]     = vf.x;
                vs[row][c8 + 2*j + 1] = vf.y;
            }
        }
        __syncthreads();

        #pragma unroll 16
        for (int s = 0; s < 64; ++s) {
            float4 kf = *(const float4*)&ks[s][td * 4];
            float4 vf = *(const float4*)&vs[s][te * 4];
            float kr[4] = {kf.x, kf.y, kf.z, kf.w};
            float vr[4] = {vf.x, vf.y, vf.z, vf.w};
            #pragma unroll
            for (int i = 0; i < 4; ++i)
                #pragma unroll
                for (int j = 0; j < 4; ++j)
                    acc[i][j] += kr[i] * vr[j];
        }
    }

    float* out = g_kvp + ((long)((b * NH + hh) * KVC + c)) * HD * HD
                       + (td * 4) * HD + te * 4;
    #pragma unroll
    for (int i = 0; i < 4; ++i)
        *(float4*)(out + i * HD) = make_float4(acc[i][0], acc[i][1], acc[i][2], acc[i][3]);
}

// ---------------------------------------------------------------------------
// MT[b, j, h*64+d] = sum_e kv[b,h,d,e] * o_w[j, h*64+e]; output rounded fp16
// ---------------------------------------------------------------------------
__global__ __launch_bounds__(256)
void make_mt(const float* __restrict__ OW)
{
    __shared__ float kvs[64][65];
    __shared__ float ows[64][64];

    const int jt = blockIdx.x, hh = blockIdx.y, b = blockIdx.z;
    const int t  = threadIdx.x;
    const int j0 = jt * 64;

    const float* pb = g_kvp + (long)((b * NH + hh) * KVC) * HD * HD;
    #pragma unroll
    for (int r = 0; r < 16; ++r) {
        int idx = t + 256 * r;
        float s = 0.0f;
        #pragma unroll
        for (int c = 0; c < KVC; ++c) s += pb[c * HD * HD + idx];
        kvs[idx >> 6][idx & 63] = s;
    }
    #pragma unroll
    for (int r = 0; r < 16; ++r) {
        int idx = t + 256 * r;
        int row = idx >> 6, e = idx & 63;
        ows[row][e] = OW[(long)(j0 + row) * DIM + hh * HD + e];
    }
    __syncthreads();

    const int d  = t & 63;
    const int rb = (t >> 6) * 16;
    float acc[16] = {};

    #pragma unroll 4
    for (int e = 0; e < 64; ++e) {
        float kd = kvs[d][e];
        #pragma unroll
        for (int jj = 0; jj < 16; ++jj)
            acc[jj] += ows[rb + jj][e] * kd;
    }

    long base = (long)b * DIM * DIM + hh * HD + d;
    #pragma unroll
    for (int jj = 0; jj < 16; ++jj)
        g_mtf[base + (long)(j0 + rb + jj) * DIM] = __float2half_rn(acc[jj]);
}

// ---------------------------------------------------------------------------
// Launch
// ---------------------------------------------------------------------------
template <typename T>
static T* sym_addr(const void* sym) {
    void* p = nullptr;
    cudaGetSymbolAddress(&p, sym);
    return (T*)p;
}

extern "C" void kernel_launch(void* const* d_in, const int* in_sizes, int n_in,
                              void* d_out, int out_size)
{
    (void)in_sizes; (void)n_in; (void)out_size;
    const float* x  = (const float*)d_in[0];
    const float* qw = (const float*)d_in[1];
    const float* qb = (const float*)d_in[2];
    const float* kw = (const float*)d_in[3];
    const float* kb = (const float*)d_in[4];
    const float* vw = (const float*)d_in[5];
    const float* vb = (const float*)d_in[6];
    const float* ow = (const float*)d_in[7];
    const float* ob = (const float*)d_in[8];
    float* y = (float*)d_out;

    __half* x16  = sym_addr<__half>(g_x16);
    __half* qw16 = sym_addr<__half>(g_qw16);
    __half* kw16 = sym_addr<__half>(g_kw16);
    __half* vw16 = sym_addr<__half>(g_vw16);

    cudaFuncSetAttribute(gemm_qkv, cudaFuncAttributeMaxDynamicSharedMemorySize, GSMEM);
    cudaFuncSetAttribute(gemm_out, cudaFuncAttributeMaxDynamicSharedMemorySize, GSMEM);

    const long NX = (long)BATCH * SEQ * DIM;   // 16.7M
    const long NW = (long)DIM * DIM;           // 1M

    // 0) round x and weights to fp16
    round_f32h<<<(int)(NX / 4 / 256), 256>>>(x, x16, NX);
    round_w3<<<dim3((int)(NW / 4 / 256), 3, 1), 256>>>(qw, kw, vw, qw16, kw16, vw16, NW);

    // 1) fused QKV projections (z selects q/k/v)
    gemm_qkv<<<dim3(DIM / TN, (BATCH * SEQ) / TM, 3), 256, GSMEM>>>(qb, kb, vb);

    // 2) kv state partials (fp16 in, fp32 accum)
    kv_partial<<<dim3(KVC, NH, BATCH), 256>>>();

    // 3) fold o_w into kv state, round to fp16
    make_mt<<<dim3(DIM / 64, NH, BATCH), 256>>>(ow);

    // 4) y[b] = q[b] @ MT[b]^T + o_b
    gemm_out<<<dim3(DIM / TN, SEQ / TM, BATCH), 256, GSMEM>>>(ob, y);
}

// round 9
// speedup vs baseline: 2.9990x; 1.1605x over previous
#include <cuda_runtime.h>
#include <cuda_fp16.h>
#include <cstdint>

// Problem constants
#define BATCH 4
#define SEQ   4096
#define DIM   1024
#define NH    16
#define HD    64
#define KVC   8               // split-S chunks for kv accumulation
#define SCH   (SEQ / KVC)     // 512

// GEMM tile config
#define GK      1024
#define TM      128
#define TN      128
#define BK      32                   // K elements per chunk
#define NCHUNK  (GK / BK)            // 32
#define RS      40                   // smem row stride in fp16 (32 data + 8 pad) = 80B
#define TILE_B  (128 * RS * 2)       // 10240 bytes per tile
#define STAGE_B (2 * TILE_B)         // A, B = 20480 bytes
#define NSTAGE  4
#define GSMEM   (NSTAGE * STAGE_B)   // 81920 bytes -> 2 CTAs/SM

// kv tile config
#define RSK     72                   // kv smem row stride halves (64 + 8 pad) = 144B
#define KVTILE  (64 * RSK * 2)       // 9216 bytes

// ---------------------------------------------------------------------------
// Scratch
// ---------------------------------------------------------------------------
__device__ __half g_x16[BATCH * SEQ * DIM];
__device__ __half g_qw16[DIM * DIM], g_kw16[DIM * DIM], g_vw16[DIM * DIM];
__device__ __half g_q16[BATCH * SEQ * DIM];
__device__ __half g_k16[BATCH * SEQ * DIM];
__device__ __half g_v16[BATCH * SEQ * DIM];
__device__ float g_kvp[BATCH * NH * KVC * HD * HD];
__device__ __half g_mtf[BATCH * DIM * DIM];

// ---------------------------------------------------------------------------
// PTX helpers
// ---------------------------------------------------------------------------
__device__ __forceinline__ uint32_t smem_u32(const void* p) {
    uint32_t a;
    asm("{ .reg .u64 t; cvta.to.shared.u64 t, %1; cvt.u32.u64 %0, t; }" : "=r"(a) : "l"(p));
    return a;
}

#define CP_ASYNC16(s, g) asm volatile("cp.async.cg.shared.global [%0], [%1], 16;" :: "r"(s), "l"(g))
#define CP_COMMIT()      asm volatile("cp.async.commit_group;" ::: "memory")
#define CP_WAIT2()       asm volatile("cp.async.wait_group 2;" ::: "memory")
#define CP_WAIT1()       asm volatile("cp.async.wait_group 1;" ::: "memory")
#define CP_WAIT0()       asm volatile("cp.async.wait_group 0;" ::: "memory")

#define LDSM_X4(r0, r1, r2, r3, a) \
    asm volatile("ldmatrix.sync.aligned.m8n8.x4.shared.b16 {%0,%1,%2,%3}, [%4];" \
                 : "=r"(r0), "=r"(r1), "=r"(r2), "=r"(r3) : "r"(a))
#define LDSM_X4_T(r0, r1, r2, r3, a) \
    asm volatile("ldmatrix.sync.aligned.m8n8.x4.trans.shared.b16 {%0,%1,%2,%3}, [%4];" \
                 : "=r"(r0), "=r"(r1), "=r"(r2), "=r"(r3) : "r"(a))

// D += A * B  (m16n8k16, fp16 in, f32 accum)
__device__ __forceinline__ void mma16816(float* c, const uint32_t* a, const uint32_t* b) {
    asm volatile(
        "mma.sync.aligned.m16n8k16.row.col.f32.f16.f16.f32 "
        "{%0,%1,%2,%3}, {%4,%5,%6,%7}, {%8,%9}, {%0,%1,%2,%3};"
        : "+f"(c[0]), "+f"(c[1]), "+f"(c[2]), "+f"(c[3])
        : "r"(a[0]), "r"(a[1]), "r"(a[2]), "r"(a[3]), "r"(b[0]), "r"(b[1]));
}

__device__ __forceinline__ uint32_t pack2h(float lo_v, float hi_v) {
    uint32_t r;
    asm("cvt.rn.f16x2.f32 %0, %1, %2;" : "=r"(r) : "f"(hi_v), "f"(lo_v));
    return r;
}

// ---------------------------------------------------------------------------
// Round kernels: fp32 -> fp16
// ---------------------------------------------------------------------------
__global__ void round_f32h(const float* __restrict__ s, __half* __restrict__ o, long n)
{
    long i = ((long)blockIdx.x * blockDim.x + threadIdx.x) * 4;
    if (i >= n) return;
    float4 v = *(const float4*)(s + i);
    *(uint2*)(o + i) = make_uint2(pack2h(v.x, v.y), pack2h(v.z, v.w));
}

__global__ void round_w3(const float* __restrict__ s0, const float* __restrict__ s1,
                         const float* __restrict__ s2,
                         __half* __restrict__ o0, __half* __restrict__ o1,
                         __half* __restrict__ o2, long n)
{
    const float* s = (blockIdx.y == 0) ? s0 : (blockIdx.y == 1) ? s1 : s2;
    __half*      o = (blockIdx.y == 0) ? o0 : (blockIdx.y == 1) ? o1 : o2;
    long i = ((long)blockIdx.x * blockDim.x + threadIdx.x) * 4;
    if (i >= n) return;
    float4 v = *(const float4*)(s + i);
    *(uint2*)(o + i) = make_uint2(pack2h(v.x, v.y), pack2h(v.z, v.w));
}

// ---------------------------------------------------------------------------
// Shared GEMM mainloop: 128 threads, 4 warps (2x2), warp tile 64x64.
// acc[4][8][4] += A_tile[m0:128,:] * B_tile[n0:128,:]^T. BK=32, 4-stage ring.
// ---------------------------------------------------------------------------
__device__ __forceinline__ void gemm_mainloop(
    const __half* __restrict__ A, const __half* __restrict__ B,
    uint32_t smem_addr, int m0, int n0, int tid, float acc[4][8][4])
{
    const int wid  = tid >> 5;
    const int lane = tid & 31;

    // cp.async geometry: tile = 128 rows x 4 (16B chunks); 4 slots/thread/tile
    uint32_t so[4];
    long ga[4], gb[4];
    #pragma unroll
    for (int i = 0; i < 4; ++i) {
        int idx = i * 128 + tid;
        int row = idx >> 2, ck = idx & 3;
        so[i] = (uint32_t)(row * RS + ck * 8) * 2;
        ga[i] = (long)(m0 + row) * GK + ck * 8;
        gb[i] = (long)(n0 + row) * GK + ck * 8;
    }

    auto load_stage = [&](int kt, int buf) {
        const uint32_t sb = smem_addr + buf * STAGE_B;
        const long ko = (long)kt * BK;
        #pragma unroll
        for (int i = 0; i < 4; ++i) CP_ASYNC16(sb + so[i],          A + ga[i] + ko);
        #pragma unroll
        for (int i = 0; i < 4; ++i) CP_ASYNC16(sb + TILE_B + so[i], B + gb[i] + ko);
    };

    load_stage(0, 0); CP_COMMIT();
    load_stage(1, 1); CP_COMMIT();
    load_stage(2, 2); CP_COMMIT();

    // Warp tiling: 2x2 warp grid, each warp 64x64
    const int wm = (wid >> 1) * 64;
    const int wn = (wid & 1) * 64;

    // ldmatrix per-lane address parts
    const uint32_t rA  = lane & 15;
    const uint32_t kAp = (uint32_t)(lane >> 4) << 4;
    const uint32_t rB  = (lane & 7) + ((lane & 16) >> 1);
    const uint32_t kBp = (lane & 8) << 1;

    uint32_t offA[4], offB[4];
    #pragma unroll
    for (int mt = 0; mt < 4; ++mt)
        offA[mt] = (uint32_t)(wm + mt * 16 + rA) * (RS * 2) + kAp;
    #pragma unroll
    for (int ntp = 0; ntp < 4; ++ntp)
        offB[ntp] = (uint32_t)(wn + ntp * 16 + rB) * (RS * 2) + kBp;

    for (int kt = 0; kt < NCHUNK; ++kt) {
        CP_WAIT2();
        __syncthreads();

        if (kt + 3 < NCHUNK) load_stage(kt + 3, (kt + 3) & 3);
        CP_COMMIT();

        const uint32_t Sb = smem_addr + (kt & 3) * STAGE_B;

        #pragma unroll
        for (int ks2 = 0; ks2 < 2; ++ks2) {
            const uint32_t kb = ks2 * 32;   // 16 k-elements = 32 bytes
            uint32_t af[4][4], bf[8][2];

            #pragma unroll
            for (int mt = 0; mt < 4; ++mt)
                LDSM_X4(af[mt][0], af[mt][1], af[mt][2], af[mt][3], Sb + kb + offA[mt]);
            #pragma unroll
            for (int ntp = 0; ntp < 4; ++ntp) {
                const uint32_t ba = Sb + TILE_B + kb + offB[ntp];
                LDSM_X4(bf[2*ntp][0], bf[2*ntp][1], bf[2*ntp+1][0], bf[2*ntp+1][1], ba);
            }

            #pragma unroll
            for (int mt = 0; mt < 4; ++mt)
                #pragma unroll
                for (int nt = 0; nt < 8; ++nt)
                    mma16816(acc[mt][nt], af[mt], bf[nt]);
        }
    }
}

// ---------------------------------------------------------------------------
// Fused QKV GEMM: blockIdx.z selects (W, bias, out, relu). fp16 out.
// ---------------------------------------------------------------------------
__global__ __launch_bounds__(128, 2)
void gemm_qkv(const float* __restrict__ qb, const float* __restrict__ kb,
              const float* __restrict__ vb)
{
    extern __shared__ char smem[];
    const uint32_t smem_addr = smem_u32(smem);

    const int tid = threadIdx.x;
    const int z   = blockIdx.z;
    const int m0  = blockIdx.y * TM;
    const int n0  = blockIdx.x * TN;

    const __half* B    = (z == 0) ? g_qw16 : (z == 1) ? g_kw16 : g_vw16;
    const float*  bias = (z == 0) ? qb     : (z == 1) ? kb     : vb;
    __half*       outH = (z == 0) ? g_q16  : (z == 1) ? g_k16  : g_v16;
    const bool    relu = (z != 2);

    float acc[4][8][4] = {};
    gemm_mainloop(g_x16, B, smem_addr, m0, n0, tid, acc);

    const int wid  = tid >> 5;
    const int lane = tid & 31;
    const int wm = (wid >> 1) * 64, wn = (wid & 1) * 64;
    const int lr = lane >> 2, lc2 = (lane & 3) * 2;

    #pragma unroll
    for (int mt = 0; mt < 4; ++mt) {
        #pragma unroll
        for (int nt = 0; nt < 8; ++nt) {
            const int row = m0 + wm + mt * 16 + lr;
            const int col = n0 + wn + nt * 8 + lc2;
            const float2 bv = *(const float2*)(bias + col);
            float v00 = acc[mt][nt][0] + bv.x, v01 = acc[mt][nt][1] + bv.y;
            float v10 = acc[mt][nt][2] + bv.x, v11 = acc[mt][nt][3] + bv.y;
            if (relu) {
                v00 = fmaxf(v00, 0.f); v01 = fmaxf(v01, 0.f);
                v10 = fmaxf(v10, 0.f); v11 = fmaxf(v11, 0.f);
            }
            const long o = (long)row * DIM + col;
            *(uint32_t*)(outH + o)            = pack2h(v00, v01);
            *(uint32_t*)(outH + o + 8L * DIM) = pack2h(v10, v11);
        }
    }
}

// ---------------------------------------------------------------------------
// Final GEMM: y[b] = q[b] @ MT[b]^T + o_b  (fp32 out)
// ---------------------------------------------------------------------------
__global__ __launch_bounds__(128, 2)
void gemm_out(const float* __restrict__ bias, float* __restrict__ outF)
{
    extern __shared__ char smem[];
    const uint32_t smem_addr = smem_u32(smem);

    const int tid = threadIdx.x;
    const int z   = blockIdx.z;
    const int m0  = blockIdx.y * TM;
    const int n0  = blockIdx.x * TN;

    const __half* A = g_q16 + (long)z * SEQ * DIM;
    const __half* B = g_mtf + (long)z * DIM * DIM;

    float acc[4][8][4] = {};
    gemm_mainloop(A, B, smem_addr, m0, n0, tid, acc);

    const int wid  = tid >> 5;
    const int lane = tid & 31;
    const int wm = (wid >> 1) * 64, wn = (wid & 1) * 64;
    const int lr = lane >> 2, lc2 = (lane & 3) * 2;

    float* out = outF + (long)z * SEQ * DIM;

    #pragma unroll
    for (int mt = 0; mt < 4; ++mt) {
        #pragma unroll
        for (int nt = 0; nt < 8; ++nt) {
            const int row = m0 + wm + mt * 16 + lr;
            const int col = n0 + wn + nt * 8 + lc2;
            const float2 bv = *(const float2*)(bias + col);
            float* p = out + (long)row * DIM + col;
            *(float2*)p              = make_float2(acc[mt][nt][0] + bv.x, acc[mt][nt][1] + bv.y);
            *(float2*)(p + 8L * DIM) = make_float2(acc[mt][nt][2] + bv.x, acc[mt][nt][3] + bv.y);
        }
    }
}

// ---------------------------------------------------------------------------
// kv partials on tensor cores: P[b,h,c,d,e] = sum_{s in chunk} k[s,d]*v[s,e].
// A = k^T (via ldmatrix.trans), B = v (k-major via trans). 128 thr, 4 warps.
// Warp n-split: each warp owns 16 e-columns; all warps share d=0..63.
// ---------------------------------------------------------------------------
__global__ __launch_bounds__(128)
void kv_mma()
{
    __shared__ __align__(16) char kvsm[2 * 2 * KVTILE];  // [buf][k/v][tile]

    const int c = blockIdx.x, hh = blockIdx.y, b = blockIdx.z;
    const int tid  = threadIdx.x;
    const int wid  = tid >> 5;
    const int lane = tid & 31;
    const uint32_t sbase = smem_u32(kvsm);

    const __half* kb = g_k16 + (long)(b * SEQ + c * SCH) * DIM + hh * HD;
    const __half* vb = g_v16 + (long)(b * SEQ + c * SCH) * DIM + hh * HD;

    // cp.async: per tile 64 rows x 8 (16B chunks) = 512 slots; 4/thread/tile
    uint32_t so[4];
    long go[4];
    #pragma unroll
    for (int i = 0; i < 4; ++i) {
        int idx = i * 128 + tid;
        int row = idx >> 3, ck = idx & 7;
        so[i] = (uint32_t)(row * RSK + ck * 8) * 2;
        go[i] = (long)row * DIM + ck * 8;
    }

    auto load_blk = [&](int blk, int buf) {
        const uint32_t sb = sbase + buf * 2 * KVTILE;
        const long ko = (long)blk * 64 * DIM;
        #pragma unroll
        for (int i = 0; i < 4; ++i) CP_ASYNC16(sb + so[i],          kb + ko + go[i]);
        #pragma unroll
        for (int i = 0; i < 4; ++i) CP_ASYNC16(sb + KVTILE + so[i], vb + ko + go[i]);
    };

    load_blk(0, 0); CP_COMMIT();

    // ldmatrix.trans address parts
    // A (k-matrix; m=d, k=s): s-row = (lane&7)+((lane&16)>>1), d-half byte = (lane&8)<<1
    const uint32_t rKA = (lane & 7) + ((lane & 16) >> 1);
    const uint32_t mAp = (lane & 8) << 1;
    // B (v-matrix; n=e, k=s): s-row = lane&15, e-half byte = (lane>>4)<<4
    const uint32_t rVB = lane & 15;
    const uint32_t nBp = (uint32_t)(lane >> 4) << 4;

    const int wn = wid * 16;   // e-range per warp

    float acc[4][2][4] = {};

    for (int blk = 0; blk < SCH / 64; ++blk) {
        if (blk + 1 < SCH / 64) load_blk(blk + 1, (blk + 1) & 1);
        CP_COMMIT();
        if (blk + 1 < SCH / 64) { CP_WAIT1(); } else { CP_WAIT0(); }
        __syncthreads();

        const uint32_t Sk = sbase + (blk & 1) * 2 * KVTILE;
        const uint32_t Sv = Sk + KVTILE;

        #pragma unroll
        for (int ks = 0; ks < 4; ++ks) {
            const uint32_t srow = ks * 16;
            uint32_t af[4][4], bf[2][2];

            #pragma unroll
            for (int mt = 0; mt < 4; ++mt) {
                const uint32_t aa = Sk + (srow + rKA) * (RSK * 2) + mt * 32 + mAp;
                LDSM_X4_T(af[mt][0], af[mt][1], af[mt][2], af[mt][3], aa);
            }
            {
                const uint32_t ba = Sv + (srow + rVB) * (RSK * 2) + wn * 2 + nBp;
                LDSM_X4_T(bf[0][0], bf[0][1], bf[1][0], bf[1][1], ba);
            }

            #pragma unroll
            for (int mt = 0; mt < 4; ++mt)
                #pragma unroll
                for (int nt = 0; nt < 2; ++nt)
                    mma16816(acc[mt][nt], af[mt], bf[nt]);
        }
        __syncthreads();   // all warps done with this buf before it is refilled
    }

    // Write fp32 partial [d][e]
    const int lr = lane >> 2, lc2 = (lane & 3) * 2;
    float* out = g_kvp + ((long)((b * NH + hh) * KVC + c)) * HD * HD;
    #pragma unroll
    for (int mt = 0; mt < 4; ++mt) {
        #pragma unroll
        for (int nt = 0; nt < 2; ++nt) {
            const int d = mt * 16 + lr;
            const int e = wn + nt * 8 + lc2;
            *(float2*)(out + (long)d * HD + e)       = make_float2(acc[mt][nt][0], acc[mt][nt][1]);
            *(float2*)(out + (long)(d + 8) * HD + e) = make_float2(acc[mt][nt][2], acc[mt][nt][3]);
        }
    }
}

// ---------------------------------------------------------------------------
// MT[b, j, h*64+d] = sum_e kv[b,h,d,e] * o_w[j, h*64+e]; output rounded fp16
// ---------------------------------------------------------------------------
__global__ __launch_bounds__(256)
void make_mt(const float* __restrict__ OW)
{
    __shared__ float kvs[64][65];
    __shared__ float ows[64][64];

    const int jt = blockIdx.x, hh = blockIdx.y, b = blockIdx.z;
    const int t  = threadIdx.x;
    const int j0 = jt * 64;

    const float* pb = g_kvp + (long)((b * NH + hh) * KVC) * HD * HD;
    #pragma unroll
    for (int r = 0; r < 16; ++r) {
        int idx = t + 256 * r;
        float s = 0.0f;
        #pragma unroll
        for (int c = 0; c < KVC; ++c) s += pb[c * HD * HD + idx];
        kvs[idx >> 6][idx & 63] = s;
    }
    #pragma unroll
    for (int r = 0; r < 16; ++r) {
        int idx = t + 256 * r;
        int row = idx >> 6, e = idx & 63;
        ows[row][e] = OW[(long)(j0 + row) * DIM + hh * HD + e];
    }
    __syncthreads();

    const int d  = t & 63;
    const int rb = (t >> 6) * 16;
    float acc[16] = {};

    #pragma unroll 4
    for (int e = 0; e < 64; ++e) {
        float kd = kvs[d][e];
        #pragma unroll
        for (int jj = 0; jj < 16; ++jj)
            acc[jj] += ows[rb + jj][e] * kd;
    }

    long base = (long)b * DIM * DIM + hh * HD + d;
    #pragma unroll
    for (int jj = 0; jj < 16; ++jj)
        g_mtf[base + (long)(j0 + rb + jj) * DIM] = __float2half_rn(acc[jj]);
}

// ---------------------------------------------------------------------------
// Launch
// ---------------------------------------------------------------------------
template <typename T>
static T* sym_addr(const void* sym) {
    void* p = nullptr;
    cudaGetSymbolAddress(&p, sym);
    return (T*)p;
}

extern "C" void kernel_launch(void* const* d_in, const int* in_sizes, int n_in,
                              void* d_out, int out_size)
{
    (void)in_sizes; (void)n_in; (void)out_size;
    const float* x  = (const float*)d_in[0];
    const float* qw = (const float*)d_in[1];
    const float* qb = (const float*)d_in[2];
    const float* kw = (const float*)d_in[3];
    const float* kb = (const float*)d_in[4];
    const float* vw = (const float*)d_in[5];
    const float* vb = (const float*)d_in[6];
    const float* ow = (const float*)d_in[7];
    const float* ob = (const float*)d_in[8];
    float* y = (float*)d_out;

    __half* x16  = sym_addr<__half>(g_x16);
    __half* qw16 = sym_addr<__half>(g_qw16);
    __half* kw16 = sym_addr<__half>(g_kw16);
    __half* vw16 = sym_addr<__half>(g_vw16);

    cudaFuncSetAttribute(gemm_qkv, cudaFuncAttributeMaxDynamicSharedMemorySize, GSMEM);
    cudaFuncSetAttribute(gemm_out, cudaFuncAttributeMaxDynamicSharedMemorySize, GSMEM);

    const long NX = (long)BATCH * SEQ * DIM;   // 16.7M
    const long NW = (long)DIM * DIM;           // 1M

    // 0) round x and weights to fp16
    round_f32h<<<(int)(NX / 4 / 256), 256>>>(x, x16, NX);
    round_w3<<<dim3((int)(NW / 4 / 256), 3, 1), 256>>>(qw, kw, vw, qw16, kw16, vw16, NW);

    // 1) fused QKV projections (z selects q/k/v)
    gemm_qkv<<<dim3(DIM / TN, (BATCH * SEQ) / TM, 3), 128, GSMEM>>>(qb, kb, vb);

    // 2) kv state partials on tensor cores
    kv_mma<<<dim3(KVC, NH, BATCH), 128>>>();

    // 3) fold o_w into kv state, round to fp16
    make_mt<<<dim3(DIM / 64, NH, BATCH), 256>>>(ow);

    // 4) y[b] = q[b] @ MT[b]^T + o_b
    gemm_out<<<dim3(DIM / TN, SEQ / TM, BATCH), 128, GSMEM>>>(ob, y);
}